// round 1
// baseline (speedup 1.0000x reference)
#include <cuda_runtime.h>
#include <cuda_fp16.h>

// Problem constants
#define BB 2
#define HH 8
#define NN 1024
#define MM 1024
#define SS 4
#define CC 64
#define DM 512
#define SCALE 0.125f   // 1/sqrt(64)

// fp16 scratch (device globals: allocation-free)
__device__ __half qh_g[(size_t)BB*HH*NN*CC];   // [bh][n][c]
__device__ __half kh_g[(size_t)BB*HH*MM*CC];   // [bh][m][c]
__device__ __half vt_g[(size_t)BB*HH*CC*MM];   // [bh][c][m]  (transposed V)

// ---------------------------------------------------------------- mma helpers
__device__ __forceinline__ unsigned smem_u32(const void* p) {
    return (unsigned)__cvta_generic_to_shared(p);
}

// A-fragment ldmatrix: 16x16 f16 tile, row-major in smem (ld = halves per row)
__device__ __forceinline__ void ldsm_x4(unsigned r[4], const __half* base,
                                        int row, int col, int ld, int lane) {
    const __half* p = base + (size_t)(row + (lane & 7) + ((lane >> 3) & 1) * 8) * ld
                           + col + (lane >> 4) * 8;
    unsigned a = smem_u32(p);
    asm volatile("ldmatrix.sync.aligned.m8n8.x4.shared.b16 {%0,%1,%2,%3},[%4];\n"
                 : "=r"(r[0]), "=r"(r[1]), "=r"(r[2]), "=r"(r[3]) : "r"(a));
}

// B-fragment ldmatrix: 16(k) x 8(n), memory layout [n][k] (k contiguous)
__device__ __forceinline__ void ldsm_x2(unsigned r[2], const __half* base,
                                        int nrow, int kcol, int ld, int lane) {
    const __half* p = base + (size_t)(nrow + (lane & 7)) * ld
                           + kcol + ((lane >> 3) & 1) * 8;
    unsigned a = smem_u32(p);
    asm volatile("ldmatrix.sync.aligned.m8n8.x2.shared.b16 {%0,%1},[%2];\n"
                 : "=r"(r[0]), "=r"(r[1]) : "r"(a));
}

__device__ __forceinline__ void mma16816(float c[4], const unsigned a[4], const unsigned b[2]) {
    asm volatile("mma.sync.aligned.m16n8k16.row.col.f32.f16.f16.f32 "
                 "{%0,%1,%2,%3},{%4,%5,%6,%7},{%8,%9},{%0,%1,%2,%3};\n"
                 : "+f"(c[0]), "+f"(c[1]), "+f"(c[2]), "+f"(c[3])
                 : "r"(a[0]), "r"(a[1]), "r"(a[2]), "r"(a[3]), "r"(b[0]), "r"(b[1]));
}

// =====================================================================
// Kernel 1: projections.  Y = X @ W^T + b  (2048 x 512 x 512), 3 matrices.
// grid: (16 row-tiles, 8 col-tiles(=head), 3 which), 256 threads.
// =====================================================================
__global__ __launch_bounds__(256)
void proj_kernel(const float* __restrict__ Xq, const float* __restrict__ Xk,
                 const float* __restrict__ Xv,
                 const float* __restrict__ Wq, const float* __restrict__ bq,
                 const float* __restrict__ Wk, const float* __restrict__ bk,
                 const float* __restrict__ Wv, const float* __restrict__ bv) {
    const int which = blockIdx.z;
    const float* X = (which == 0) ? Xq : (which == 1) ? Xk : Xv;
    const float* W = (which == 0) ? Wq : (which == 1) ? Wk : Wv;
    const float* bias = (which == 0) ? bq : (which == 1) ? bk : bv;

    __shared__ __half As[128 * 72];
    __shared__ __half Bs[64 * 72];

    const int row0 = blockIdx.x * 128;
    const int j0 = blockIdx.y * 64;          // one head per CTA column-tile
    const int tid = threadIdx.x;
    const int warp = tid >> 5, lane = tid & 31;
    const int wn = warp & 3, wc = warp >> 2; // 4x2 warp grid, 32x32 warp tiles

    float acc[2][4][4] = {};

    for (int kc = 0; kc < DM; kc += 64) {
        // stage A: 128x64 f32 -> f16 (pad 72)
        #pragma unroll
        for (int it = 0; it < 8; it++) {
            int idx = tid + it * 256;            // 2048 float4
            int r = idx >> 4, cf = (idx & 15) << 2;
            float4 v = __ldg(reinterpret_cast<const float4*>(
                X + (size_t)(row0 + r) * DM + kc + cf));
            __half2* dst = reinterpret_cast<__half2*>(&As[r * 72 + cf]);
            dst[0] = __floats2half2_rn(v.x, v.y);
            dst[1] = __floats2half2_rn(v.z, v.w);
        }
        // stage B: 64x64 (j rows, d cols)
        #pragma unroll
        for (int it = 0; it < 4; it++) {
            int idx = tid + it * 256;            // 1024 float4
            int r = idx >> 4, cf = (idx & 15) << 2;
            float4 v = __ldg(reinterpret_cast<const float4*>(
                W + (size_t)(j0 + r) * DM + kc + cf));
            __half2* dst = reinterpret_cast<__half2*>(&Bs[r * 72 + cf]);
            dst[0] = __floats2half2_rn(v.x, v.y);
            dst[1] = __floats2half2_rn(v.z, v.w);
        }
        __syncthreads();
        #pragma unroll
        for (int kt = 0; kt < 4; kt++) {
            unsigned af[2][4], bf[4][2];
            #pragma unroll
            for (int mt = 0; mt < 2; mt++)
                ldsm_x4(af[mt], As, wn * 32 + mt * 16, kt * 16, 72, lane);
            #pragma unroll
            for (int nt = 0; nt < 4; nt++)
                ldsm_x2(bf[nt], Bs, wc * 32 + nt * 8, kt * 16, 72, lane);
            #pragma unroll
            for (int mt = 0; mt < 2; mt++)
                #pragma unroll
                for (int nt = 0; nt < 4; nt++)
                    mma16816(acc[mt][nt], af[mt], bf[nt]);
        }
        __syncthreads();
    }

    const int h = j0 >> 6;
    #pragma unroll
    for (int mt = 0; mt < 2; mt++) {
        int rg = row0 + wn * 32 + mt * 16 + (lane >> 2);
        #pragma unroll
        for (int nt = 0; nt < 4; nt++) {
            int j = j0 + wc * 32 + nt * 8 + 2 * (lane & 3);
            float b0 = __ldg(bias + j), b1 = __ldg(bias + j + 1);
            #pragma unroll
            for (int hr = 0; hr < 2; hr++) {
                int r = rg + hr * 8;
                int bi = r >> 10, seq = r & 1023;
                float v0 = acc[mt][nt][hr * 2 + 0] + b0;
                float v1 = acc[mt][nt][hr * 2 + 1] + b1;
                int c = j & 63;
                size_t bh = (size_t)(bi * HH + h);
                if (which == 2) {
                    vt_g[(bh * CC + c) * MM + seq]     = __float2half_rn(v0);
                    vt_g[(bh * CC + c + 1) * MM + seq] = __float2half_rn(v1);
                } else {
                    __half* dst = (which == 0) ? qh_g : kh_g;
                    *reinterpret_cast<__half2*>(&dst[(bh * NN + seq) * CC + c]) =
                        __floats2half2_rn(v0, v1);
                }
            }
        }
    }
}

// =====================================================================
// Kernel 2: G = q @ k^T once per (b,h,n-tile); per-s softmax; write attn.
// grid: (32 n-tiles, H, B), 256 threads, 154,624 B dyn smem.
// =====================================================================
#define K2_SMEM (32 * 1028 * 4 + 32 * 72 * 2 + 128 * 72 * 2)

__global__ __launch_bounds__(256)
void attn_kernel(float* __restrict__ attn_out,
                 const float* __restrict__ qsub, const float* __restrict__ ksub) {
    extern __shared__ char smem[];
    float*  Gs = reinterpret_cast<float*>(smem);                         // 32 x 1028
    __half* qs = reinterpret_cast<__half*>(smem + 32 * 1028 * 4);        // 32 x 72
    __half* ks = reinterpret_cast<__half*>(smem + 32 * 1028 * 4 + 32 * 72 * 2); // 128 x 72

    const int n0 = blockIdx.x * 32;
    const int h = blockIdx.y, b = blockIdx.z;
    const size_t bh = (size_t)b * HH + h;
    const int tid = threadIdx.x, warp = tid >> 5, lane = tid & 31;

    // stage q tile (32 x 64 f16)
    {
        int r = tid >> 3, u = tid & 7;
        *reinterpret_cast<uint4*>(&qs[r * 72 + u * 8]) =
            *reinterpret_cast<const uint4*>(qh_g + (bh * NN + n0 + r) * CC + u * 8);
    }
    __syncthreads();

    unsigned afr[2][4][4];
    #pragma unroll
    for (int mt = 0; mt < 2; mt++)
        #pragma unroll
        for (int kt = 0; kt < 4; kt++)
            ldsm_x4(afr[mt][kt], qs, mt * 16, kt * 16, 72, lane);

    // QK: loop m-chunks of 128; each warp computes a 16-col slice
    for (int mc = 0; mc < 8; mc++) {
        __syncthreads();
        #pragma unroll
        for (int it = 0; it < 4; it++) {
            int idx = tid + it * 256;   // 1024 uint4: 128 rows x 8
            int r = idx >> 3, u = idx & 7;
            *reinterpret_cast<uint4*>(&ks[r * 72 + u * 8]) =
                *reinterpret_cast<const uint4*>(
                    kh_g + (bh * MM + mc * 128 + r) * CC + u * 8);
        }
        __syncthreads();
        float acc[2][2][4] = {};
        #pragma unroll
        for (int kt = 0; kt < 4; kt++) {
            unsigned bfr[2][2];
            #pragma unroll
            for (int nt = 0; nt < 2; nt++)
                ldsm_x2(bfr[nt], ks, warp * 16 + nt * 8, kt * 16, 72, lane);
            #pragma unroll
            for (int mt = 0; mt < 2; mt++)
                #pragma unroll
                for (int nt = 0; nt < 2; nt++)
                    mma16816(acc[mt][nt], afr[mt][kt], bfr[nt]);
        }
        #pragma unroll
        for (int mt = 0; mt < 2; mt++)
            #pragma unroll
            for (int nt = 0; nt < 2; nt++) {
                int r = mt * 16 + (lane >> 2);
                int cidx = mc * 128 + warp * 16 + nt * 8 + 2 * (lane & 3);
                Gs[r * 1028 + cidx]           = acc[mt][nt][0];
                Gs[r * 1028 + cidx + 1]       = acc[mt][nt][1];
                Gs[(r + 8) * 1028 + cidx]     = acc[mt][nt][2];
                Gs[(r + 8) * 1028 + cidx + 1] = acc[mt][nt][3];
            }
    }
    __syncthreads();

    // softmax: warp w owns rows 4w..4w+3; one exp per element, all in regs
    for (int s = 0; s < SS; s++) {
        const float* ksub_s = ksub + ((size_t)b * SS + s) * MM;
        #pragma unroll
        for (int rr = 0; rr < 4; rr++) {
            int row = warp * 4 + rr;
            int n = n0 + row;
            float cs = SCALE * __ldg(qsub + ((size_t)b * SS + s) * NN + n);
            float4 t[8];
            float rmax = -1e30f;
            #pragma unroll
            for (int j = 0; j < 8; j++) {
                int m = j * 128 + lane * 4;
                float4 g = *reinterpret_cast<const float4*>(&Gs[row * 1028 + m]);
                float4 d = __ldg(reinterpret_cast<const float4*>(ksub_s + m));
                t[j].x = cs * d.x * g.x;  t[j].y = cs * d.y * g.y;
                t[j].z = cs * d.z * g.z;  t[j].w = cs * d.w * g.w;
                rmax = fmaxf(rmax, fmaxf(fmaxf(t[j].x, t[j].y), fmaxf(t[j].z, t[j].w)));
            }
            #pragma unroll
            for (int o = 16; o; o >>= 1)
                rmax = fmaxf(rmax, __shfl_xor_sync(0xffffffffu, rmax, o));
            float sum = 0.f;
            #pragma unroll
            for (int j = 0; j < 8; j++) {
                t[j].x = __expf(t[j].x - rmax);  t[j].y = __expf(t[j].y - rmax);
                t[j].z = __expf(t[j].z - rmax);  t[j].w = __expf(t[j].w - rmax);
                sum += (t[j].x + t[j].y) + (t[j].z + t[j].w);
            }
            #pragma unroll
            for (int o = 16; o; o >>= 1)
                sum += __shfl_xor_sync(0xffffffffu, sum, o);
            float inv = 1.f / sum;
            float* orow = attn_out + (((bh * SS + s) * NN + n) * (size_t)MM);
            #pragma unroll
            for (int j = 0; j < 8; j++) {
                float4 o4 = make_float4(t[j].x * inv, t[j].y * inv,
                                        t[j].z * inv, t[j].w * inv);
                *reinterpret_cast<float4*>(orow + j * 128 + lane * 4) = o4;
            }
        }
    }
}

// =====================================================================
// Kernel 3: hidden = attn @ V.  Per (b,h,s): 1024 x 64 x 1024 GEMM.
// grid: (8 n-tiles, 64 bhs), 256 threads.
// =====================================================================
__global__ __launch_bounds__(256)
void av_kernel(float* __restrict__ out, const float* __restrict__ attn) {
    const int n0 = blockIdx.x * 128;
    const int y = blockIdx.y;
    const int b = y >> 5, h = (y >> 2) & 7, s = y & 3;
    const size_t bh = (size_t)b * HH + h;
    const float* A = attn + ((bh * SS + s) * NN) * (size_t)MM;  // [n][m]
    const __half* V = vt_g + bh * CC * MM;                      // [c][m]

    __shared__ __half As[128 * 72];
    __shared__ __half Bs[64 * 72];

    const int tid = threadIdx.x, warp = tid >> 5, lane = tid & 31;
    const int wn = warp >> 1, wc = warp & 1;   // 4x2 warps, 32x32 tiles

    float acc[2][4][4] = {};

    for (int kc = 0; kc < MM; kc += 64) {
        #pragma unroll
        for (int it = 0; it < 8; it++) {
            int idx = tid + it * 256;           // 2048 float4
            int r = idx >> 4, cf = (idx & 15) << 2;
            float4 v = __ldg(reinterpret_cast<const float4*>(
                A + (size_t)(n0 + r) * MM + kc + cf));
            __half2* dst = reinterpret_cast<__half2*>(&As[r * 72 + cf]);
            dst[0] = __floats2half2_rn(v.x, v.y);
            dst[1] = __floats2half2_rn(v.z, v.w);
        }
        #pragma unroll
        for (int it = 0; it < 2; it++) {
            int idx = tid + it * 256;           // 512 uint4: 64 rows x 8
            int r = idx >> 3, u = idx & 7;
            *reinterpret_cast<uint4*>(&Bs[r * 72 + u * 8]) =
                *reinterpret_cast<const uint4*>(V + (size_t)r * MM + kc + u * 8);
        }
        __syncthreads();
        #pragma unroll
        for (int kt = 0; kt < 4; kt++) {
            unsigned af[2][4], bf[4][2];
            #pragma unroll
            for (int mt = 0; mt < 2; mt++)
                ldsm_x4(af[mt], As, wn * 32 + mt * 16, kt * 16, 72, lane);
            #pragma unroll
            for (int nt = 0; nt < 4; nt++)
                ldsm_x2(bf[nt], Bs, wc * 32 + nt * 8, kt * 16, 72, lane);
            #pragma unroll
            for (int mt = 0; mt < 2; mt++)
                #pragma unroll
                for (int nt = 0; nt < 4; nt++)
                    mma16816(acc[mt][nt], af[mt], bf[nt]);
        }
        __syncthreads();
    }

    #pragma unroll
    for (int mt = 0; mt < 2; mt++) {
        #pragma unroll
        for (int nt = 0; nt < 4; nt++) {
            int c = wc * 32 + nt * 8 + 2 * (lane & 3);
            #pragma unroll
            for (int hr = 0; hr < 2; hr++) {
                int n_g = n0 + wn * 32 + mt * 16 + (lane >> 2) + hr * 8;
                size_t ob = (((size_t)(b * SS + s) * NN + n_g)) * DM + h * 64 + c;
                *reinterpret_cast<float2*>(&out[ob]) =
                    make_float2(acc[mt][nt][hr * 2 + 0], acc[mt][nt][hr * 2 + 1]);
            }
        }
    }
}

// =====================================================================
extern "C" void kernel_launch(void* const* d_in, const int* in_sizes, int n_in,
                              void* d_out, int out_size) {
    (void)in_sizes; (void)n_in; (void)out_size;
    const float* Xq   = (const float*)d_in[0];
    const float* Xk   = (const float*)d_in[1];
    const float* Xv   = (const float*)d_in[2];
    const float* qsub = (const float*)d_in[3];
    const float* ksub = (const float*)d_in[4];
    const float* Wq   = (const float*)d_in[5];
    const float* bq   = (const float*)d_in[6];
    const float* Wk   = (const float*)d_in[7];
    const float* bk   = (const float*)d_in[8];
    const float* Wv   = (const float*)d_in[9];
    const float* bv   = (const float*)d_in[10];

    float* out = (float*)d_out;
    float* attn_out = out + (size_t)BB * SS * NN * DM;  // hidden first, attn second

    cudaFuncSetAttribute(attn_kernel, cudaFuncAttributeMaxDynamicSharedMemorySize, K2_SMEM);

    proj_kernel<<<dim3(16, 8, 3), 256>>>(Xq, Xk, Xv, Wq, bq, Wk, bk, Wv, bv);
    attn_kernel<<<dim3(32, 8, 2), 256, K2_SMEM>>>(attn_out, qsub, ksub);
    av_kernel<<<dim3(8, 64), 256>>>(out, attn_out);
}

// round 2
// speedup vs baseline: 1.0135x; 1.0135x over previous
#include <cuda_runtime.h>
#include <cuda_fp16.h>

// Problem constants
#define BB 2
#define HH 8
#define NN 1024
#define MM 1024
#define SS 4
#define CC 64
#define DM 512
#define SCALE 0.125f   // 1/sqrt(64)

// fp16 scratch (device globals: allocation-free)
__device__ __half qh_g[(size_t)BB*HH*NN*CC];   // [bh][n][c]
__device__ __half kh_g[(size_t)BB*HH*MM*CC];   // [bh][m][c]
__device__ __half vt_g[(size_t)BB*HH*CC*MM];   // [bh][c][m]  (transposed V)

// ---------------------------------------------------------------- mma helpers
__device__ __forceinline__ unsigned smem_u32(const void* p) {
    return (unsigned)__cvta_generic_to_shared(p);
}

// A-fragment ldmatrix: 16x16 f16 tile, row-major in smem (ld = halves per row)
__device__ __forceinline__ void ldsm_x4(unsigned r[4], const __half* base,
                                        int row, int col, int ld, int lane) {
    const __half* p = base + (size_t)(row + (lane & 7) + ((lane >> 3) & 1) * 8) * ld
                           + col + (lane >> 4) * 8;
    unsigned a = smem_u32(p);
    asm volatile("ldmatrix.sync.aligned.m8n8.x4.shared.b16 {%0,%1,%2,%3},[%4];\n"
                 : "=r"(r[0]), "=r"(r[1]), "=r"(r[2]), "=r"(r[3]) : "r"(a));
}

// B-fragment ldmatrix: 16(k) x 8(n), memory layout [n][k] (k contiguous)
__device__ __forceinline__ void ldsm_x2(unsigned r[2], const __half* base,
                                        int nrow, int kcol, int ld, int lane) {
    const __half* p = base + (size_t)(nrow + (lane & 7)) * ld
                           + kcol + ((lane >> 3) & 1) * 8;
    unsigned a = smem_u32(p);
    asm volatile("ldmatrix.sync.aligned.m8n8.x2.shared.b16 {%0,%1},[%2];\n"
                 : "=r"(r[0]), "=r"(r[1]) : "r"(a));
}

__device__ __forceinline__ void mma16816(float c[4], const unsigned a[4], const unsigned b[2]) {
    asm volatile("mma.sync.aligned.m16n8k16.row.col.f32.f16.f16.f32 "
                 "{%0,%1,%2,%3},{%4,%5,%6,%7},{%8,%9},{%0,%1,%2,%3};\n"
                 : "+f"(c[0]), "+f"(c[1]), "+f"(c[2]), "+f"(c[3])
                 : "r"(a[0]), "r"(a[1]), "r"(a[2]), "r"(a[3]), "r"(b[0]), "r"(b[1]));
}

// =====================================================================
// Kernel 1: projections.  Y = X @ W^T + b  (2048 x 512 x 512), 3 matrices.
// grid: (16 row-tiles, 8 col-tiles(=head), 3 which), 256 threads.
// Software-pipelined: prefetch next fp32 tiles into regs during mma.
// =====================================================================
__global__ __launch_bounds__(256)
void proj_kernel(const float* __restrict__ Xq, const float* __restrict__ Xk,
                 const float* __restrict__ Xv,
                 const float* __restrict__ Wq, const float* __restrict__ bq,
                 const float* __restrict__ Wk, const float* __restrict__ bk,
                 const float* __restrict__ Wv, const float* __restrict__ bv) {
    const int which = blockIdx.z;
    const float* X = (which == 0) ? Xq : (which == 1) ? Xk : Xv;
    const float* W = (which == 0) ? Wq : (which == 1) ? Wk : Wv;
    const float* bias = (which == 0) ? bq : (which == 1) ? bk : bv;

    __shared__ __half As[128 * 72];
    __shared__ __half Bs[64 * 72];

    const int row0 = blockIdx.x * 128;
    const int j0 = blockIdx.y * 64;          // one head per CTA column-tile
    const int tid = threadIdx.x;
    const int warp = tid >> 5, lane = tid & 31;
    const int wn = warp & 3, wc = warp >> 2; // 4x2 warp grid, 32x32 warp tiles

    float acc[2][4][4] = {};
    float4 ra[8], rb[4];

    // prefetch tile 0
    #pragma unroll
    for (int it = 0; it < 8; it++) {
        int idx = tid + it * 256;
        int r = idx >> 4, cf = (idx & 15) << 2;
        ra[it] = __ldg(reinterpret_cast<const float4*>(X + (size_t)(row0 + r) * DM + cf));
    }
    #pragma unroll
    for (int it = 0; it < 4; it++) {
        int idx = tid + it * 256;
        int r = idx >> 4, cf = (idx & 15) << 2;
        rb[it] = __ldg(reinterpret_cast<const float4*>(W + (size_t)(j0 + r) * DM + cf));
    }

    for (int kc8 = 0; kc8 < 8; kc8++) {
        // store current tile regs -> smem (convert to f16)
        #pragma unroll
        for (int it = 0; it < 8; it++) {
            int idx = tid + it * 256;
            int r = idx >> 4, cf = (idx & 15) << 2;
            __half2* dst = reinterpret_cast<__half2*>(&As[r * 72 + cf]);
            dst[0] = __floats2half2_rn(ra[it].x, ra[it].y);
            dst[1] = __floats2half2_rn(ra[it].z, ra[it].w);
        }
        #pragma unroll
        for (int it = 0; it < 4; it++) {
            int idx = tid + it * 256;
            int r = idx >> 4, cf = (idx & 15) << 2;
            __half2* dst = reinterpret_cast<__half2*>(&Bs[r * 72 + cf]);
            dst[0] = __floats2half2_rn(rb[it].x, rb[it].y);
            dst[1] = __floats2half2_rn(rb[it].z, rb[it].w);
        }
        __syncthreads();

        // prefetch next tile (overlaps with mma below)
        if (kc8 < 7) {
            int kc = (kc8 + 1) * 64;
            #pragma unroll
            for (int it = 0; it < 8; it++) {
                int idx = tid + it * 256;
                int r = idx >> 4, cf = (idx & 15) << 2;
                ra[it] = __ldg(reinterpret_cast<const float4*>(
                    X + (size_t)(row0 + r) * DM + kc + cf));
            }
            #pragma unroll
            for (int it = 0; it < 4; it++) {
                int idx = tid + it * 256;
                int r = idx >> 4, cf = (idx & 15) << 2;
                rb[it] = __ldg(reinterpret_cast<const float4*>(
                    W + (size_t)(j0 + r) * DM + kc + cf));
            }
        }

        #pragma unroll
        for (int kt = 0; kt < 4; kt++) {
            unsigned af[2][4], bf[4][2];
            #pragma unroll
            for (int mt = 0; mt < 2; mt++)
                ldsm_x4(af[mt], As, wn * 32 + mt * 16, kt * 16, 72, lane);
            #pragma unroll
            for (int nt = 0; nt < 4; nt++)
                ldsm_x2(bf[nt], Bs, wc * 32 + nt * 8, kt * 16, 72, lane);
            #pragma unroll
            for (int mt = 0; mt < 2; mt++)
                #pragma unroll
                for (int nt = 0; nt < 4; nt++)
                    mma16816(acc[mt][nt], af[mt], bf[nt]);
        }
        __syncthreads();
    }

    const int h = j0 >> 6;
    #pragma unroll
    for (int mt = 0; mt < 2; mt++) {
        int rg = row0 + wn * 32 + mt * 16 + (lane >> 2);
        #pragma unroll
        for (int nt = 0; nt < 4; nt++) {
            int j = j0 + wc * 32 + nt * 8 + 2 * (lane & 3);
            float b0 = __ldg(bias + j), b1 = __ldg(bias + j + 1);
            #pragma unroll
            for (int hr = 0; hr < 2; hr++) {
                int r = rg + hr * 8;
                int bi = r >> 10, seq = r & 1023;
                float v0 = acc[mt][nt][hr * 2 + 0] + b0;
                float v1 = acc[mt][nt][hr * 2 + 1] + b1;
                int c = j & 63;
                size_t bh = (size_t)(bi * HH + h);
                if (which == 2) {
                    vt_g[(bh * CC + c) * MM + seq]     = __float2half_rn(v0);
                    vt_g[(bh * CC + c + 1) * MM + seq] = __float2half_rn(v1);
                } else {
                    __half* dst = (which == 0) ? qh_g : kh_g;
                    *reinterpret_cast<__half2*>(&dst[(bh * NN + seq) * CC + c]) =
                        __floats2half2_rn(v0, v1);
                }
            }
        }
    }
}

// =====================================================================
// Kernel 2 (FUSED): per (b,h, 32 n-rows):
//   G = q @ k^T (once, reused for all 4 subspaces);
//   per-s: softmax -> write attn + stage P fp16 -> hidden = P @ V^T.
// grid: (32 n-tiles, H, B), 512 threads (16 warps).
// =====================================================================
// smem offsets (bytes)
#define GS_OFF   0
#define QS_OFF   (32 * 1028 * 4)                 // 131584
#define KS_OFF   (QS_OFF + 32 * 72 * 2)          // 136192
#define PS_OFF   (KS_OFF + 9216 * 2)             // 154624
#define K2_SMEM  (PS_OFF + 32 * 1032 * 2)        // 220672

__global__ __launch_bounds__(512)
void attn_kernel(float* __restrict__ hidden_out, float* __restrict__ attn_out,
                 const float* __restrict__ qsub, const float* __restrict__ ksub) {
    extern __shared__ char smem[];
    float*  Gs = reinterpret_cast<float*>(smem + GS_OFF);   // 32 x 1028 f32
    __half* qs = reinterpret_cast<__half*>(smem + QS_OFF);  // 32 x 72 f16
    __half* ks = reinterpret_cast<__half*>(smem + KS_OFF);  // K: 128x72 / V: 64x136
    __half* Ps = reinterpret_cast<__half*>(smem + PS_OFF);  // 32 x 1032 f16

    const int n0 = blockIdx.x * 32;
    const int h = blockIdx.y, b = blockIdx.z;
    const size_t bh = (size_t)b * HH + h;
    const int tid = threadIdx.x, warp = tid >> 5, lane = tid & 31;

    // stage q tile (32 x 64 f16): 256 uint4
    if (tid < 256) {
        int r = tid >> 3, u = tid & 7;
        *reinterpret_cast<uint4*>(&qs[r * 72 + u * 8]) =
            *reinterpret_cast<const uint4*>(qh_g + (bh * NN + n0 + r) * CC + u * 8);
    }
    __syncthreads();

    unsigned afr[2][4][4];
    #pragma unroll
    for (int mt = 0; mt < 2; mt++)
        #pragma unroll
        for (int kt = 0; kt < 4; kt++)
            ldsm_x4(afr[mt][kt], qs, mt * 16, kt * 16, 72, lane);

    // ---- QK: loop m-chunks of 128; warp w computes the 8-col slice w*8 ----
    for (int mc = 0; mc < 8; mc++) {
        __syncthreads();
        #pragma unroll
        for (int it = 0; it < 2; it++) {
            int idx = tid + it * 512;   // 1024 uint4: 128 rows x 8
            int r = idx >> 3, u = idx & 7;
            *reinterpret_cast<uint4*>(&ks[r * 72 + u * 8]) =
                *reinterpret_cast<const uint4*>(
                    kh_g + (bh * MM + mc * 128 + r) * CC + u * 8);
        }
        __syncthreads();
        float acc[2][4] = {};
        #pragma unroll
        for (int kt = 0; kt < 4; kt++) {
            unsigned bfr[2];
            ldsm_x2(bfr, ks, warp * 8, kt * 16, 72, lane);
            #pragma unroll
            for (int mt = 0; mt < 2; mt++)
                mma16816(acc[mt], afr[mt][kt], bfr);
        }
        #pragma unroll
        for (int mt = 0; mt < 2; mt++) {
            int r = mt * 16 + (lane >> 2);
            int cidx = mc * 128 + warp * 8 + 2 * (lane & 3);
            Gs[r * 1028 + cidx]           = acc[mt][0];
            Gs[r * 1028 + cidx + 1]       = acc[mt][1];
            Gs[(r + 8) * 1028 + cidx]     = acc[mt][2];
            Gs[(r + 8) * 1028 + cidx + 1] = acc[mt][3];
        }
    }
    __syncthreads();

    // ---- per-subspace: softmax + attn write + P stage + AV GEMM ----
    const int av_mt = warp >> 3;   // 0..1 : 16-row tile
    const int av_ct = warp & 7;    // 0..7 : 8-col tile

    for (int s = 0; s < SS; s++) {
        const float* ksub_s = ksub + ((size_t)b * SS + s) * MM;
        // warp owns rows 2*warp .. 2*warp+1
        #pragma unroll
        for (int rr = 0; rr < 2; rr++) {
            int row = warp * 2 + rr;
            int n = n0 + row;
            float cs = SCALE * __ldg(qsub + ((size_t)b * SS + s) * NN + n);
            float4 t[8];
            float rmax = -1e30f;
            #pragma unroll
            for (int j = 0; j < 8; j++) {
                int m = j * 128 + lane * 4;
                float4 g = *reinterpret_cast<const float4*>(&Gs[row * 1028 + m]);
                float4 d = __ldg(reinterpret_cast<const float4*>(ksub_s + m));
                t[j].x = cs * d.x * g.x;  t[j].y = cs * d.y * g.y;
                t[j].z = cs * d.z * g.z;  t[j].w = cs * d.w * g.w;
                rmax = fmaxf(rmax, fmaxf(fmaxf(t[j].x, t[j].y), fmaxf(t[j].z, t[j].w)));
            }
            #pragma unroll
            for (int o = 16; o; o >>= 1)
                rmax = fmaxf(rmax, __shfl_xor_sync(0xffffffffu, rmax, o));
            float sum = 0.f;
            #pragma unroll
            for (int j = 0; j < 8; j++) {
                t[j].x = __expf(t[j].x - rmax);  t[j].y = __expf(t[j].y - rmax);
                t[j].z = __expf(t[j].z - rmax);  t[j].w = __expf(t[j].w - rmax);
                sum += (t[j].x + t[j].y) + (t[j].z + t[j].w);
            }
            #pragma unroll
            for (int o = 16; o; o >>= 1)
                sum += __shfl_xor_sync(0xffffffffu, sum, o);
            float inv = 1.f / sum;
            float* orow = attn_out + (((bh * SS + s) * NN + n) * (size_t)MM);
            #pragma unroll
            for (int j = 0; j < 8; j++) {
                int m = j * 128 + lane * 4;
                float4 o4 = make_float4(t[j].x * inv, t[j].y * inv,
                                        t[j].z * inv, t[j].w * inv);
                *reinterpret_cast<float4*>(orow + m) = o4;
                __half2* pd = reinterpret_cast<__half2*>(&Ps[row * 1032 + m]);
                pd[0] = __floats2half2_rn(o4.x, o4.y);
                pd[1] = __floats2half2_rn(o4.z, o4.w);
            }
        }
        __syncthreads();

        // AV GEMM: hidden[32x64] = P[32x1024] @ Vt[64x1024]^T
        float acc2[4] = {};
        for (int mc = 0; mc < 8; mc++) {
            // load V chunk: 64 c-rows x 128 m, f16, stride 136
            #pragma unroll
            for (int it = 0; it < 2; it++) {
                int idx = tid + it * 512;   // 1024 uint4: 64 rows x 16
                int r = idx >> 4, u = idx & 15;
                *reinterpret_cast<uint4*>(&ks[r * 136 + u * 8]) =
                    *reinterpret_cast<const uint4*>(
                        vt_g + (bh * CC + r) * MM + mc * 128 + u * 8);
            }
            __syncthreads();
            #pragma unroll
            for (int kt = 0; kt < 8; kt++) {
                unsigned af[4], bf[2];
                ldsm_x4(af, Ps, av_mt * 16, mc * 128 + kt * 16, 1032, lane);
                ldsm_x2(bf, ks, av_ct * 8, kt * 16, 136, lane);
                mma16816(acc2, af, bf);
            }
            __syncthreads();
        }
        // write hidden tile: rows av_mt*16 + (lane>>2) (+8), cols av_ct*8 + 2*(lane&3)
        {
            int c = av_ct * 8 + 2 * (lane & 3);
            int n_g0 = n0 + av_mt * 16 + (lane >> 2);
            size_t base = ((size_t)(b * SS + s) * NN) * DM + h * 64 + c;
            *reinterpret_cast<float2*>(&hidden_out[base + (size_t)n_g0 * DM]) =
                make_float2(acc2[0], acc2[1]);
            *reinterpret_cast<float2*>(&hidden_out[base + (size_t)(n_g0 + 8) * DM]) =
                make_float2(acc2[2], acc2[3]);
        }
        __syncthreads();   // protect Ps before next s rewrites it
    }
}

// =====================================================================
extern "C" void kernel_launch(void* const* d_in, const int* in_sizes, int n_in,
                              void* d_out, int out_size) {
    (void)in_sizes; (void)n_in; (void)out_size;
    const float* Xq   = (const float*)d_in[0];
    const float* Xk   = (const float*)d_in[1];
    const float* Xv   = (const float*)d_in[2];
    const float* qsub = (const float*)d_in[3];
    const float* ksub = (const float*)d_in[4];
    const float* Wq   = (const float*)d_in[5];
    const float* bq   = (const float*)d_in[6];
    const float* Wk   = (const float*)d_in[7];
    const float* bk   = (const float*)d_in[8];
    const float* Wv   = (const float*)d_in[9];
    const float* bv   = (const float*)d_in[10];

    float* out = (float*)d_out;
    float* attn_out = out + (size_t)BB * SS * NN * DM;  // hidden first, attn second

    cudaFuncSetAttribute(attn_kernel, cudaFuncAttributeMaxDynamicSharedMemorySize, K2_SMEM);

    proj_kernel<<<dim3(16, 8, 3), 256>>>(Xq, Xk, Xv, Wq, bq, Wk, bk, Wv, bv);
    attn_kernel<<<dim3(32, 8, 2), 512, K2_SMEM>>>(out, attn_out, qsub, ksub);
}

// round 3
// speedup vs baseline: 1.5480x; 1.5275x over previous
#include <cuda_runtime.h>
#include <cuda_fp16.h>

// Problem constants
#define BB 2
#define HH 8
#define NN 1024
#define MM 1024
#define SS 4
#define CC 64
#define DM 512
#define SCALE 0.125f   // 1/sqrt(64)

// fp16 scratch (device globals: allocation-free)
__device__ __half qh_g[(size_t)BB*HH*NN*CC];   // [bh][n][c]
__device__ __half kh_g[(size_t)BB*HH*MM*CC];   // [bh][m][c]
__device__ __half vt_g[(size_t)BB*HH*CC*MM];   // [bh][c][m]  (transposed V)

// ---------------------------------------------------------------- mma helpers
__device__ __forceinline__ unsigned smem_u32(const void* p) {
    return (unsigned)__cvta_generic_to_shared(p);
}

// A-fragment ldmatrix: 16x16 f16 tile, row-major in smem (ld = halves per row)
__device__ __forceinline__ void ldsm_x4(unsigned r[4], const __half* base,
                                        int row, int col, int ld, int lane) {
    const __half* p = base + (size_t)(row + (lane & 7) + ((lane >> 3) & 1) * 8) * ld
                           + col + (lane >> 4) * 8;
    unsigned a = smem_u32(p);
    asm volatile("ldmatrix.sync.aligned.m8n8.x4.shared.b16 {%0,%1,%2,%3},[%4];\n"
                 : "=r"(r[0]), "=r"(r[1]), "=r"(r[2]), "=r"(r[3]) : "r"(a));
}

// B-fragment ldmatrix: 16(k) x 8(n), memory layout [n][k] (k contiguous)
__device__ __forceinline__ void ldsm_x2(unsigned r[2], const __half* base,
                                        int nrow, int kcol, int ld, int lane) {
    const __half* p = base + (size_t)(nrow + (lane & 7)) * ld
                           + kcol + ((lane >> 3) & 1) * 8;
    unsigned a = smem_u32(p);
    asm volatile("ldmatrix.sync.aligned.m8n8.x2.shared.b16 {%0,%1},[%2];\n"
                 : "=r"(r[0]), "=r"(r[1]) : "r"(a));
}

__device__ __forceinline__ void mma16816(float c[4], const unsigned a[4], const unsigned b[2]) {
    asm volatile("mma.sync.aligned.m16n8k16.row.col.f32.f16.f16.f32 "
                 "{%0,%1,%2,%3},{%4,%5,%6,%7},{%8,%9},{%0,%1,%2,%3};\n"
                 : "+f"(c[0]), "+f"(c[1]), "+f"(c[2]), "+f"(c[3])
                 : "r"(a[0]), "r"(a[1]), "r"(a[2]), "r"(a[3]), "r"(b[0]), "r"(b[1]));
}

// =====================================================================
// Kernel 1: projections.  Y = X @ W^T + b  (2048 x 512 x 512), 3 matrices.
// grid: (16 row-tiles, 8 col-tiles(=head), 3 which), 256 threads.
// =====================================================================
__global__ __launch_bounds__(256)
void proj_kernel(const float* __restrict__ Xq, const float* __restrict__ Xk,
                 const float* __restrict__ Xv,
                 const float* __restrict__ Wq, const float* __restrict__ bq,
                 const float* __restrict__ Wk, const float* __restrict__ bk,
                 const float* __restrict__ Wv, const float* __restrict__ bv) {
    const int which = blockIdx.z;
    const float* X = (which == 0) ? Xq : (which == 1) ? Xk : Xv;
    const float* W = (which == 0) ? Wq : (which == 1) ? Wk : Wv;
    const float* bias = (which == 0) ? bq : (which == 1) ? bk : bv;

    __shared__ __half As[128 * 72];
    __shared__ __half Bs[64 * 72];

    const int row0 = blockIdx.x * 128;
    const int j0 = blockIdx.y * 64;
    const int tid = threadIdx.x;
    const int warp = tid >> 5, lane = tid & 31;
    const int wn = warp & 3, wc = warp >> 2;

    float acc[2][4][4] = {};
    float4 ra[8], rb[4];

    #pragma unroll
    for (int it = 0; it < 8; it++) {
        int idx = tid + it * 256;
        int r = idx >> 4, cf = (idx & 15) << 2;
        ra[it] = __ldg(reinterpret_cast<const float4*>(X + (size_t)(row0 + r) * DM + cf));
    }
    #pragma unroll
    for (int it = 0; it < 4; it++) {
        int idx = tid + it * 256;
        int r = idx >> 4, cf = (idx & 15) << 2;
        rb[it] = __ldg(reinterpret_cast<const float4*>(W + (size_t)(j0 + r) * DM + cf));
    }

    for (int kc8 = 0; kc8 < 8; kc8++) {
        #pragma unroll
        for (int it = 0; it < 8; it++) {
            int idx = tid + it * 256;
            int r = idx >> 4, cf = (idx & 15) << 2;
            __half2* dst = reinterpret_cast<__half2*>(&As[r * 72 + cf]);
            dst[0] = __floats2half2_rn(ra[it].x, ra[it].y);
            dst[1] = __floats2half2_rn(ra[it].z, ra[it].w);
        }
        #pragma unroll
        for (int it = 0; it < 4; it++) {
            int idx = tid + it * 256;
            int r = idx >> 4, cf = (idx & 15) << 2;
            __half2* dst = reinterpret_cast<__half2*>(&Bs[r * 72 + cf]);
            dst[0] = __floats2half2_rn(rb[it].x, rb[it].y);
            dst[1] = __floats2half2_rn(rb[it].z, rb[it].w);
        }
        __syncthreads();

        if (kc8 < 7) {
            int kc = (kc8 + 1) * 64;
            #pragma unroll
            for (int it = 0; it < 8; it++) {
                int idx = tid + it * 256;
                int r = idx >> 4, cf = (idx & 15) << 2;
                ra[it] = __ldg(reinterpret_cast<const float4*>(
                    X + (size_t)(row0 + r) * DM + kc + cf));
            }
            #pragma unroll
            for (int it = 0; it < 4; it++) {
                int idx = tid + it * 256;
                int r = idx >> 4, cf = (idx & 15) << 2;
                rb[it] = __ldg(reinterpret_cast<const float4*>(
                    W + (size_t)(j0 + r) * DM + kc + cf));
            }
        }

        #pragma unroll
        for (int kt = 0; kt < 4; kt++) {
            unsigned af[2][4], bf[4][2];
            #pragma unroll
            for (int mt = 0; mt < 2; mt++)
                ldsm_x4(af[mt], As, wn * 32 + mt * 16, kt * 16, 72, lane);
            #pragma unroll
            for (int nt = 0; nt < 4; nt++)
                ldsm_x2(bf[nt], Bs, wc * 32 + nt * 8, kt * 16, 72, lane);
            #pragma unroll
            for (int mt = 0; mt < 2; mt++)
                #pragma unroll
                for (int nt = 0; nt < 4; nt++)
                    mma16816(acc[mt][nt], af[mt], bf[nt]);
        }
        __syncthreads();
    }

    const int h = j0 >> 6;
    #pragma unroll
    for (int mt = 0; mt < 2; mt++) {
        int rg = row0 + wn * 32 + mt * 16 + (lane >> 2);
        #pragma unroll
        for (int nt = 0; nt < 4; nt++) {
            int j = j0 + wc * 32 + nt * 8 + 2 * (lane & 3);
            float b0 = __ldg(bias + j), b1 = __ldg(bias + j + 1);
            #pragma unroll
            for (int hr = 0; hr < 2; hr++) {
                int r = rg + hr * 8;
                int bi = r >> 10, seq = r & 1023;
                float v0 = acc[mt][nt][hr * 2 + 0] + b0;
                float v1 = acc[mt][nt][hr * 2 + 1] + b1;
                int c = j & 63;
                size_t bh = (size_t)(bi * HH + h);
                if (which == 2) {
                    vt_g[(bh * CC + c) * MM + seq]     = __float2half_rn(v0);
                    vt_g[(bh * CC + c + 1) * MM + seq] = __float2half_rn(v1);
                } else {
                    __half* dst = (which == 0) ? qh_g : kh_g;
                    *reinterpret_cast<__half2*>(&dst[(bh * NN + seq) * CC + c]) =
                        __floats2half2_rn(v0, v1);
                }
            }
        }
    }
}

// =====================================================================
// Kernel 2 (FUSED, 16-row tiles, 2 CTAs/SM):
//   QK -> Gs(f32);  pass A: row sums (no max, exp#1);
//   pass B: per m-chunk: stage V once, recompute e (exp#2), write attn,
//           stage P(e*inv) fp16 for 4 s, mma with k-split across warp pairs.
// grid: (64 n-tiles, H, B) = 1024 CTAs, 512 threads.
// =====================================================================
#define GS_STRIDE 1032
#define GS_OFF   0
#define KV_OFF   (16 * GS_STRIDE * 4)            // 66048
#define PS_OFF   (KV_OFF + 128 * 72 * 2)         // 66048 + 18432 = 84480
#define QS_OFF   (PS_OFF + 4 * 16 * 136 * 2)     // 84480 + 17408 = 101888
#define K2_SMEM  (QS_OFF + 16 * 72 * 2)          // 104192

__global__ __launch_bounds__(512, 2)
void attn_kernel(float* __restrict__ hidden_out, float* __restrict__ attn_out,
                 const float* __restrict__ qsub, const float* __restrict__ ksub) {
    extern __shared__ char smem[];
    float*  Gs = reinterpret_cast<float*>(smem + GS_OFF);   // 16 x 1032 f32
    __half* kv = reinterpret_cast<__half*>(smem + KV_OFF);  // K:128x72 / V:64x136
    __half* Ps = reinterpret_cast<__half*>(smem + PS_OFF);  // [4][16][136] f16
    __half* qs = reinterpret_cast<__half*>(smem + QS_OFF);  // 16 x 72 f16
    float*  red = reinterpret_cast<float*>(smem + KV_OFF);  // reduction (reuses kv)

    const int n0 = blockIdx.x * 16;
    const int h = blockIdx.y, b = blockIdx.z;
    const size_t bh = (size_t)b * HH + h;
    const int tid = threadIdx.x, warp = tid >> 5, lane = tid & 31;

    // stage q tile (16 x 64 f16): 128 uint4
    if (tid < 128) {
        int r = tid >> 3, u = tid & 7;
        *reinterpret_cast<uint4*>(&qs[r * 72 + u * 8]) =
            *reinterpret_cast<const uint4*>(qh_g + (bh * NN + n0 + r) * CC + u * 8);
    }
    __syncthreads();

    unsigned afr[4][4];
    #pragma unroll
    for (int kt = 0; kt < 4; kt++)
        ldsm_x4(afr[kt], qs, 0, kt * 16, 72, lane);

    // ---- QK: 16 x 1024. Per mc chunk of 128 m, warp w computes cols w*8..w*8+7
    for (int mc = 0; mc < 8; mc++) {
        if (mc) __syncthreads();
        #pragma unroll
        for (int it = 0; it < 2; it++) {
            int idx = tid + it * 512;   // 1024 uint4: 128 rows x 8
            int r = idx >> 3, u = idx & 7;
            *reinterpret_cast<uint4*>(&kv[r * 72 + u * 8]) =
                *reinterpret_cast<const uint4*>(
                    kh_g + (bh * MM + mc * 128 + r) * CC + u * 8);
        }
        __syncthreads();
        float acc[4] = {};
        #pragma unroll
        for (int kt = 0; kt < 4; kt++) {
            unsigned bfr[2];
            ldsm_x2(bfr, kv, warp * 8, kt * 16, 72, lane);
            mma16816(acc, afr[kt], bfr);
        }
        int r = lane >> 2;
        int c0 = mc * 128 + warp * 8 + 2 * (lane & 3);
        Gs[r * GS_STRIDE + c0]           = acc[0];
        Gs[r * GS_STRIDE + c0 + 1]       = acc[1];
        Gs[(r + 8) * GS_STRIDE + c0]     = acc[2];
        Gs[(r + 8) * GS_STRIDE + c0 + 1] = acc[3];
    }
    __syncthreads();

    // ---- pass A: row sums (warp w owns row w). No max subtraction: scores bounded.
    float cs[4], inv[4];
    #pragma unroll
    for (int s = 0; s < SS; s++)
        cs[s] = SCALE * __ldg(qsub + ((size_t)b * SS + s) * NN + n0 + warp);

    {
        float sum[4] = {0.f, 0.f, 0.f, 0.f};
        #pragma unroll
        for (int j = 0; j < 8; j++) {
            int m = j * 128 + lane * 4;
            float4 g = *reinterpret_cast<const float4*>(&Gs[warp * GS_STRIDE + m]);
            #pragma unroll
            for (int s = 0; s < SS; s++) {
                float4 d = __ldg(reinterpret_cast<const float4*>(
                    ksub + ((size_t)b * SS + s) * MM + m));
                sum[s] += __expf(cs[s] * d.x * g.x) + __expf(cs[s] * d.y * g.y)
                        + __expf(cs[s] * d.z * g.z) + __expf(cs[s] * d.w * g.w);
            }
        }
        #pragma unroll
        for (int s = 0; s < SS; s++) {
            #pragma unroll
            for (int o = 16; o; o >>= 1)
                sum[s] += __shfl_xor_sync(0xffffffffu, sum[s], o);
            inv[s] = 1.f / sum[s];
        }
    }

    // ---- pass B: per mc: stage V once, e=exp (scaled by inv), write attn,
    //      stage Ps for all 4 s, then mma (warps split k: w<8 -> kt 0-3, w>=8 -> 4-7)
    float accB[4][4] = {};
    const int ct = warp & 7;        // output col tile (8 cols of 64)
    const int kh_ = warp >> 3;      // k-half

    for (int mc = 0; mc < 8; mc++) {
        __syncthreads();   // previous iteration's mma reads of kv/Ps complete
        #pragma unroll
        for (int it = 0; it < 2; it++) {
            int idx = tid + it * 512;   // 1024 uint4: 64 rows x 16
            int r = idx >> 4, u = idx & 15;
            *reinterpret_cast<uint4*>(&kv[r * 136 + u * 8]) =
                *reinterpret_cast<const uint4*>(
                    vt_g + (bh * CC + r) * MM + mc * 128 + u * 8);
        }
        {
            int m = mc * 128 + lane * 4;
            float4 g = *reinterpret_cast<const float4*>(&Gs[warp * GS_STRIDE + m]);
            #pragma unroll
            for (int s = 0; s < SS; s++) {
                float4 d = __ldg(reinterpret_cast<const float4*>(
                    ksub + ((size_t)b * SS + s) * MM + m));
                float4 e;
                e.x = __expf(cs[s] * d.x * g.x) * inv[s];
                e.y = __expf(cs[s] * d.y * g.y) * inv[s];
                e.z = __expf(cs[s] * d.z * g.z) * inv[s];
                e.w = __expf(cs[s] * d.w * g.w) * inv[s];
                *reinterpret_cast<float4*>(
                    attn_out + ((bh * SS + s) * NN + n0 + warp) * (size_t)MM + m) = e;
                __half2 p0 = __floats2half2_rn(e.x, e.y);
                __half2 p1 = __floats2half2_rn(e.z, e.w);
                *reinterpret_cast<__half2*>(&Ps[(s * 16 + warp) * 136 + lane * 4])     = p0;
                *reinterpret_cast<__half2*>(&Ps[(s * 16 + warp) * 136 + lane * 4 + 2]) = p1;
            }
        }
        __syncthreads();
        #pragma unroll
        for (int kt = 0; kt < 4; kt++) {
            int kk = kh_ * 4 + kt;
            unsigned bf[2];
            ldsm_x2(bf, kv, ct * 8, kk * 16, 136, lane);
            #pragma unroll
            for (int s = 0; s < SS; s++) {
                unsigned af[4];
                ldsm_x4(af, Ps + s * 16 * 136, 0, kk * 16, 136, lane);
                mma16816(accB[s], af, bf);
            }
        }
    }
    __syncthreads();

    // k-split reduction + hidden write
    if (warp >= 8) {
        #pragma unroll
        for (int s = 0; s < SS; s++)
            *reinterpret_cast<float4*>(&red[(((warp - 8) * 4 + s) * 32 + lane) * 4]) =
                make_float4(accB[s][0], accB[s][1], accB[s][2], accB[s][3]);
    }
    __syncthreads();
    if (warp < 8) {
        #pragma unroll
        for (int s = 0; s < SS; s++) {
            float4 p = *reinterpret_cast<const float4*>(
                &red[((warp * 4 + s) * 32 + lane) * 4]);
            float v0 = accB[s][0] + p.x, v1 = accB[s][1] + p.y;
            float v2 = accB[s][2] + p.z, v3 = accB[s][3] + p.w;
            int r0 = lane >> 2;
            int c = ct * 8 + 2 * (lane & 3);
            size_t base = ((size_t)(b * SS + s) * NN + n0) * DM + h * 64 + c;
            *reinterpret_cast<float2*>(&hidden_out[base + (size_t)r0 * DM]) =
                make_float2(v0, v1);
            *reinterpret_cast<float2*>(&hidden_out[base + (size_t)(r0 + 8) * DM]) =
                make_float2(v2, v3);
        }
    }
}

// =====================================================================
extern "C" void kernel_launch(void* const* d_in, const int* in_sizes, int n_in,
                              void* d_out, int out_size) {
    (void)in_sizes; (void)n_in; (void)out_size;
    const float* Xq   = (const float*)d_in[0];
    const float* Xk   = (const float*)d_in[1];
    const float* Xv   = (const float*)d_in[2];
    const float* qsub = (const float*)d_in[3];
    const float* ksub = (const float*)d_in[4];
    const float* Wq   = (const float*)d_in[5];
    const float* bq   = (const float*)d_in[6];
    const float* Wk   = (const float*)d_in[7];
    const float* bk   = (const float*)d_in[8];
    const float* Wv   = (const float*)d_in[9];
    const float* bv   = (const float*)d_in[10];

    float* out = (float*)d_out;
    float* attn_out = out + (size_t)BB * SS * NN * DM;  // hidden first, attn second

    cudaFuncSetAttribute(attn_kernel, cudaFuncAttributeMaxDynamicSharedMemorySize, K2_SMEM);

    proj_kernel<<<dim3(16, 8, 3), 256>>>(Xq, Xk, Xv, Wq, bq, Wk, bk, Wv, bv);
    attn_kernel<<<dim3(64, 8, 2), 512, K2_SMEM>>>(out, attn_out, qsub, ksub);
}

// round 4
// speedup vs baseline: 1.6685x; 1.0779x over previous
#include <cuda_runtime.h>
#include <cuda_fp16.h>

// Problem constants
#define BB 2
#define HH 8
#define NN 1024
#define MM 1024
#define SS 4
#define CC 64
#define DM 512
#define SCALE 0.125f   // 1/sqrt(64)

// fp16 scratch (device globals: allocation-free)
__device__ __half qh_g[(size_t)BB*HH*NN*CC];   // [bh][n][c]
__device__ __half kh_g[(size_t)BB*HH*MM*CC];   // [bh][m][c]
__device__ __half vt_g[(size_t)BB*HH*CC*MM];   // [bh][c][m]  (transposed V)

// ---------------------------------------------------------------- mma helpers
__device__ __forceinline__ unsigned smem_u32(const void* p) {
    return (unsigned)__cvta_generic_to_shared(p);
}

__device__ __forceinline__ void ldsm_x4(unsigned r[4], const __half* base,
                                        int row, int col, int ld, int lane) {
    const __half* p = base + (size_t)(row + (lane & 7) + ((lane >> 3) & 1) * 8) * ld
                           + col + (lane >> 4) * 8;
    unsigned a = smem_u32(p);
    asm volatile("ldmatrix.sync.aligned.m8n8.x4.shared.b16 {%0,%1,%2,%3},[%4];\n"
                 : "=r"(r[0]), "=r"(r[1]), "=r"(r[2]), "=r"(r[3]) : "r"(a));
}

__device__ __forceinline__ void ldsm_x2(unsigned r[2], const __half* base,
                                        int nrow, int kcol, int ld, int lane) {
    const __half* p = base + (size_t)(nrow + (lane & 7)) * ld
                           + kcol + ((lane >> 3) & 1) * 8;
    unsigned a = smem_u32(p);
    asm volatile("ldmatrix.sync.aligned.m8n8.x2.shared.b16 {%0,%1},[%2];\n"
                 : "=r"(r[0]), "=r"(r[1]) : "r"(a));
}

__device__ __forceinline__ void mma16816(float c[4], const unsigned a[4], const unsigned b[2]) {
    asm volatile("mma.sync.aligned.m16n8k16.row.col.f32.f16.f16.f32 "
                 "{%0,%1,%2,%3},{%4,%5,%6,%7},{%8,%9},{%0,%1,%2,%3};\n"
                 : "+f"(c[0]), "+f"(c[1]), "+f"(c[2]), "+f"(c[3])
                 : "r"(a[0]), "r"(a[1]), "r"(a[2]), "r"(a[3]), "r"(b[0]), "r"(b[1]));
}

// =====================================================================
// Kernel 1: projections.  Y = X @ W^T + b  (2048 x 512 x 512), 3 matrices.
// =====================================================================
__global__ __launch_bounds__(256)
void proj_kernel(const float* __restrict__ Xq, const float* __restrict__ Xk,
                 const float* __restrict__ Xv,
                 const float* __restrict__ Wq, const float* __restrict__ bq,
                 const float* __restrict__ Wk, const float* __restrict__ bk,
                 const float* __restrict__ Wv, const float* __restrict__ bv) {
    const int which = blockIdx.z;
    const float* X = (which == 0) ? Xq : (which == 1) ? Xk : Xv;
    const float* W = (which == 0) ? Wq : (which == 1) ? Wk : Wv;
    const float* bias = (which == 0) ? bq : (which == 1) ? bk : bv;

    __shared__ __half As[128 * 72];
    __shared__ __half Bs[64 * 72];

    const int row0 = blockIdx.x * 128;
    const int j0 = blockIdx.y * 64;
    const int tid = threadIdx.x;
    const int warp = tid >> 5, lane = tid & 31;
    const int wn = warp & 3, wc = warp >> 2;

    float acc[2][4][4] = {};
    float4 ra[8], rb[4];

    #pragma unroll
    for (int it = 0; it < 8; it++) {
        int idx = tid + it * 256;
        int r = idx >> 4, cf = (idx & 15) << 2;
        ra[it] = __ldg(reinterpret_cast<const float4*>(X + (size_t)(row0 + r) * DM + cf));
    }
    #pragma unroll
    for (int it = 0; it < 4; it++) {
        int idx = tid + it * 256;
        int r = idx >> 4, cf = (idx & 15) << 2;
        rb[it] = __ldg(reinterpret_cast<const float4*>(W + (size_t)(j0 + r) * DM + cf));
    }

    for (int kc8 = 0; kc8 < 8; kc8++) {
        #pragma unroll
        for (int it = 0; it < 8; it++) {
            int idx = tid + it * 256;
            int r = idx >> 4, cf = (idx & 15) << 2;
            __half2* dst = reinterpret_cast<__half2*>(&As[r * 72 + cf]);
            dst[0] = __floats2half2_rn(ra[it].x, ra[it].y);
            dst[1] = __floats2half2_rn(ra[it].z, ra[it].w);
        }
        #pragma unroll
        for (int it = 0; it < 4; it++) {
            int idx = tid + it * 256;
            int r = idx >> 4, cf = (idx & 15) << 2;
            __half2* dst = reinterpret_cast<__half2*>(&Bs[r * 72 + cf]);
            dst[0] = __floats2half2_rn(rb[it].x, rb[it].y);
            dst[1] = __floats2half2_rn(rb[it].z, rb[it].w);
        }
        __syncthreads();

        if (kc8 < 7) {
            int kc = (kc8 + 1) * 64;
            #pragma unroll
            for (int it = 0; it < 8; it++) {
                int idx = tid + it * 256;
                int r = idx >> 4, cf = (idx & 15) << 2;
                ra[it] = __ldg(reinterpret_cast<const float4*>(
                    X + (size_t)(row0 + r) * DM + kc + cf));
            }
            #pragma unroll
            for (int it = 0; it < 4; it++) {
                int idx = tid + it * 256;
                int r = idx >> 4, cf = (idx & 15) << 2;
                rb[it] = __ldg(reinterpret_cast<const float4*>(
                    W + (size_t)(j0 + r) * DM + kc + cf));
            }
        }

        #pragma unroll
        for (int kt = 0; kt < 4; kt++) {
            unsigned af[2][4], bf[4][2];
            #pragma unroll
            for (int mt = 0; mt < 2; mt++)
                ldsm_x4(af[mt], As, wn * 32 + mt * 16, kt * 16, 72, lane);
            #pragma unroll
            for (int nt = 0; nt < 4; nt++)
                ldsm_x2(bf[nt], Bs, wc * 32 + nt * 8, kt * 16, 72, lane);
            #pragma unroll
            for (int mt = 0; mt < 2; mt++)
                #pragma unroll
                for (int nt = 0; nt < 4; nt++)
                    mma16816(acc[mt][nt], af[mt], bf[nt]);
        }
        __syncthreads();
    }

    const int h = j0 >> 6;
    #pragma unroll
    for (int mt = 0; mt < 2; mt++) {
        int rg = row0 + wn * 32 + mt * 16 + (lane >> 2);
        #pragma unroll
        for (int nt = 0; nt < 4; nt++) {
            int j = j0 + wc * 32 + nt * 8 + 2 * (lane & 3);
            float b0 = __ldg(bias + j), b1 = __ldg(bias + j + 1);
            #pragma unroll
            for (int hr = 0; hr < 2; hr++) {
                int r = rg + hr * 8;
                int bi = r >> 10, seq = r & 1023;
                float v0 = acc[mt][nt][hr * 2 + 0] + b0;
                float v1 = acc[mt][nt][hr * 2 + 1] + b1;
                int c = j & 63;
                size_t bh = (size_t)(bi * HH + h);
                if (which == 2) {
                    vt_g[(bh * CC + c) * MM + seq]     = __float2half_rn(v0);
                    vt_g[(bh * CC + c + 1) * MM + seq] = __float2half_rn(v1);
                } else {
                    __half* dst = (which == 0) ? qh_g : kh_g;
                    *reinterpret_cast<__half2*>(&dst[(bh * NN + seq) * CC + c]) =
                        __floats2half2_rn(v0, v1);
                }
            }
        }
    }
}

// =====================================================================
// Kernel 2 (FUSED): QK -> Gs f32; pass A sums; pass B: exp+attn write+AV.
//   ksub staged in smem fp16 once; K/V chunks register-prefetched.
// grid: (64 n-tiles, H, B) = 1024 CTAs, 512 threads, 2 CTAs/SM.
// =====================================================================
#define GS_STRIDE 1032
#define GS_OFF   0
#define KV_OFF   (16 * GS_STRIDE * 4)            // 66048
#define PS_OFF   (KV_OFF + 128 * 72 * 2)         // 84480
#define QS_OFF   (PS_OFF + 4 * 16 * 136 * 2)     // 101888
#define US_OFF   (QS_OFF + 16 * 72 * 2)          // 104192
#define US_STRIDE 1056
#define K2_SMEM  (US_OFF + 4 * US_STRIDE * 2)    // 112640

__global__ __launch_bounds__(512, 2)
void attn_kernel(float* __restrict__ hidden_out, float* __restrict__ attn_out,
                 const float* __restrict__ qsub, const float* __restrict__ ksub) {
    extern __shared__ char smem[];
    float*  Gs = reinterpret_cast<float*>(smem + GS_OFF);   // 16 x 1032 f32
    __half* kv = reinterpret_cast<__half*>(smem + KV_OFF);  // K:128x72 / V:64x136
    __half* Ps = reinterpret_cast<__half*>(smem + PS_OFF);  // [4][16][136] f16
    __half* qs = reinterpret_cast<__half*>(smem + QS_OFF);  // 16 x 72 f16
    __half* us = reinterpret_cast<__half*>(smem + US_OFF);  // ksub fp16 [4][1056]
    float*  red = reinterpret_cast<float*>(smem + KV_OFF);  // reduction (reuses kv)

    const int n0 = blockIdx.x * 16;
    const int h = blockIdx.y, b = blockIdx.z;
    const size_t bh = (size_t)b * HH + h;
    const int tid = threadIdx.x, warp = tid >> 5, lane = tid & 31;

    // prefetch K chunk 0 into regs
    uint4 pk[2];
    #pragma unroll
    for (int it = 0; it < 2; it++) {
        int idx = tid + it * 512;
        int r = idx >> 3, u = idx & 7;
        pk[it] = *reinterpret_cast<const uint4*>(kh_g + (bh * MM + r) * CC + u * 8);
    }
    // stage q tile (16 x 64 f16): 128 uint4
    if (tid < 128) {
        int r = tid >> 3, u = tid & 7;
        *reinterpret_cast<uint4*>(&qs[r * 72 + u * 8]) =
            *reinterpret_cast<const uint4*>(qh_g + (bh * NN + n0 + r) * CC + u * 8);
    }
    // stage ksub fp16: 4 x 1024 floats, 2 float4 per thread
    #pragma unroll
    for (int it = 0; it < 2; it++) {
        int idx = tid + it * 512;
        int s = idx >> 8, mf = (idx & 255) << 2;
        float4 d = __ldg(reinterpret_cast<const float4*>(
            ksub + ((size_t)b * SS + s) * MM + mf));
        __half2* dst = reinterpret_cast<__half2*>(&us[s * US_STRIDE + mf]);
        dst[0] = __floats2half2_rn(d.x, d.y);
        dst[1] = __floats2half2_rn(d.z, d.w);
    }
    __syncthreads();

    unsigned afr[4][4];
    #pragma unroll
    for (int kt = 0; kt < 4; kt++)
        ldsm_x4(afr[kt], qs, 0, kt * 16, 72, lane);

    // ---- QK: per 128-m chunk, warp w computes cols w*8..w*8+7 ----
    for (int mc = 0; mc < 8; mc++) {
        if (mc) __syncthreads();   // prev mma reads of kv done
        #pragma unroll
        for (int it = 0; it < 2; it++) {
            int idx = tid + it * 512;
            int r = idx >> 3, u = idx & 7;
            *reinterpret_cast<uint4*>(&kv[r * 72 + u * 8]) = pk[it];
        }
        __syncthreads();
        if (mc < 7) {
            #pragma unroll
            for (int it = 0; it < 2; it++) {
                int idx = tid + it * 512;
                int r = idx >> 3, u = idx & 7;
                pk[it] = *reinterpret_cast<const uint4*>(
                    kh_g + (bh * MM + (mc + 1) * 128 + r) * CC + u * 8);
            }
        }
        float acc[4] = {};
        #pragma unroll
        for (int kt = 0; kt < 4; kt++) {
            unsigned bfr[2];
            ldsm_x2(bfr, kv, warp * 8, kt * 16, 72, lane);
            mma16816(acc, afr[kt], bfr);
        }
        int r = lane >> 2;
        int c0 = mc * 128 + warp * 8 + 2 * (lane & 3);
        Gs[r * GS_STRIDE + c0]           = acc[0];
        Gs[r * GS_STRIDE + c0 + 1]       = acc[1];
        Gs[(r + 8) * GS_STRIDE + c0]     = acc[2];
        Gs[(r + 8) * GS_STRIDE + c0 + 1] = acc[3];
    }
    __syncthreads();

    // prefetch V chunk 0 (overlaps pass A compute)
    uint4 pv[2];
    #pragma unroll
    for (int it = 0; it < 2; it++) {
        int idx = tid + it * 512;
        int r = idx >> 4, u = idx & 15;
        pv[it] = *reinterpret_cast<const uint4*>(vt_g + (bh * CC + r) * MM + u * 8);
    }

    // ---- pass A: row sums (warp w owns row w); ksub from smem fp16 ----
    float cs[4], inv[4];
    #pragma unroll
    for (int s = 0; s < SS; s++)
        cs[s] = SCALE * __ldg(qsub + ((size_t)b * SS + s) * NN + n0 + warp);

    {
        float sum[4] = {0.f, 0.f, 0.f, 0.f};
        #pragma unroll
        for (int j = 0; j < 8; j++) {
            int m = j * 128 + lane * 4;
            float4 g = *reinterpret_cast<const float4*>(&Gs[warp * GS_STRIDE + m]);
            #pragma unroll
            for (int s = 0; s < SS; s++) {
                const __half2* dp = reinterpret_cast<const __half2*>(&us[s * US_STRIDE + m]);
                float2 d01 = __half22float2(dp[0]);
                float2 d23 = __half22float2(dp[1]);
                sum[s] += __expf(cs[s] * d01.x * g.x) + __expf(cs[s] * d01.y * g.y)
                        + __expf(cs[s] * d23.x * g.z) + __expf(cs[s] * d23.y * g.w);
            }
        }
        #pragma unroll
        for (int s = 0; s < SS; s++) {
            #pragma unroll
            for (int o = 16; o; o >>= 1)
                sum[s] += __shfl_xor_sync(0xffffffffu, sum[s], o);
            inv[s] = 1.f / sum[s];
        }
    }

    // ---- pass B ----
    float accB[4][4] = {};
    const int ct = warp & 7;
    const int kh_ = warp >> 3;

    for (int mc = 0; mc < 8; mc++) {
        if (mc) __syncthreads();   // prev mma reads of kv/Ps done
        #pragma unroll
        for (int it = 0; it < 2; it++) {
            int idx = tid + it * 512;
            int r = idx >> 4, u = idx & 15;
            *reinterpret_cast<uint4*>(&kv[r * 136 + u * 8]) = pv[it];
        }
        {
            int m = mc * 128 + lane * 4;
            float4 g = *reinterpret_cast<const float4*>(&Gs[warp * GS_STRIDE + m]);
            #pragma unroll
            for (int s = 0; s < SS; s++) {
                const __half2* dp = reinterpret_cast<const __half2*>(&us[s * US_STRIDE + m]);
                float2 d01 = __half22float2(dp[0]);
                float2 d23 = __half22float2(dp[1]);
                float4 e;
                e.x = __expf(cs[s] * d01.x * g.x) * inv[s];
                e.y = __expf(cs[s] * d01.y * g.y) * inv[s];
                e.z = __expf(cs[s] * d23.x * g.z) * inv[s];
                e.w = __expf(cs[s] * d23.y * g.w) * inv[s];
                *reinterpret_cast<float4*>(
                    attn_out + ((bh * SS + s) * NN + n0 + warp) * (size_t)MM + m) = e;
                __half2* pd = reinterpret_cast<__half2*>(&Ps[(s * 16 + warp) * 136 + lane * 4]);
                pd[0] = __floats2half2_rn(e.x, e.y);
                pd[1] = __floats2half2_rn(e.z, e.w);
            }
        }
        __syncthreads();
        if (mc < 7) {
            #pragma unroll
            for (int it = 0; it < 2; it++) {
                int idx = tid + it * 512;
                int r = idx >> 4, u = idx & 15;
                pv[it] = *reinterpret_cast<const uint4*>(
                    vt_g + (bh * CC + r) * MM + (mc + 1) * 128 + u * 8);
            }
        }
        #pragma unroll
        for (int kt = 0; kt < 4; kt++) {
            int kk = kh_ * 4 + kt;
            unsigned bf[2];
            ldsm_x2(bf, kv, ct * 8, kk * 16, 136, lane);
            #pragma unroll
            for (int s = 0; s < SS; s++) {
                unsigned af[4];
                ldsm_x4(af, Ps + s * 16 * 136, 0, kk * 16, 136, lane);
                mma16816(accB[s], af, bf);
            }
        }
    }
    __syncthreads();

    // k-split reduction + hidden write
    if (warp >= 8) {
        #pragma unroll
        for (int s = 0; s < SS; s++)
            *reinterpret_cast<float4*>(&red[(((warp - 8) * 4 + s) * 32 + lane) * 4]) =
                make_float4(accB[s][0], accB[s][1], accB[s][2], accB[s][3]);
    }
    __syncthreads();
    if (warp < 8) {
        #pragma unroll
        for (int s = 0; s < SS; s++) {
            float4 p = *reinterpret_cast<const float4*>(
                &red[((warp * 4 + s) * 32 + lane) * 4]);
            float v0 = accB[s][0] + p.x, v1 = accB[s][1] + p.y;
            float v2 = accB[s][2] + p.z, v3 = accB[s][3] + p.w;
            int r0 = lane >> 2;
            int c = ct * 8 + 2 * (lane & 3);
            size_t base = ((size_t)(b * SS + s) * NN + n0) * DM + h * 64 + c;
            *reinterpret_cast<float2*>(&hidden_out[base + (size_t)r0 * DM]) =
                make_float2(v0, v1);
            *reinterpret_cast<float2*>(&hidden_out[base + (size_t)(r0 + 8) * DM]) =
                make_float2(v2, v3);
        }
    }
}

// =====================================================================
extern "C" void kernel_launch(void* const* d_in, const int* in_sizes, int n_in,
                              void* d_out, int out_size) {
    (void)in_sizes; (void)n_in; (void)out_size;
    const float* Xq   = (const float*)d_in[0];
    const float* Xk   = (const float*)d_in[1];
    const float* Xv   = (const float*)d_in[2];
    const float* qsub = (const float*)d_in[3];
    const float* ksub = (const float*)d_in[4];
    const float* Wq   = (const float*)d_in[5];
    const float* bq   = (const float*)d_in[6];
    const float* Wk   = (const float*)d_in[7];
    const float* bk   = (const float*)d_in[8];
    const float* Wv   = (const float*)d_in[9];
    const float* bv   = (const float*)d_in[10];

    float* out = (float*)d_out;
    float* attn_out = out + (size_t)BB * SS * NN * DM;  // hidden first, attn second

    cudaFuncSetAttribute(attn_kernel, cudaFuncAttributeMaxDynamicSharedMemorySize, K2_SMEM);

    proj_kernel<<<dim3(16, 8, 3), 256>>>(Xq, Xk, Xv, Wq, bq, Wk, bk, Wv, bv);
    attn_kernel<<<dim3(64, 8, 2), 512, K2_SMEM>>>(out, attn_out, qsub, ksub);
}

// round 6
// speedup vs baseline: 1.7967x; 1.0768x over previous
#include <cuda_runtime.h>
#include <cuda_fp16.h>

// Problem constants
#define BB 2
#define HH 8
#define NN 1024
#define MM 1024
#define SS 4
#define CC 64
#define DM 512
#define SCALE 0.125f   // 1/sqrt(64)

// fp16 scratch (device globals: allocation-free)
__device__ __half qh_g[(size_t)BB*HH*NN*CC];   // [bh][n][c]
__device__ __half kh_g[(size_t)BB*HH*MM*CC];   // [bh][m][c]
__device__ __half vt_g[(size_t)BB*HH*CC*MM];   // [bh][c][m]  (transposed V)

// ---------------------------------------------------------------- mma helpers
__device__ __forceinline__ unsigned smem_u32(const void* p) {
    return (unsigned)__cvta_generic_to_shared(p);
}

__device__ __forceinline__ void ldsm_x4(unsigned r[4], const __half* base,
                                        int row, int col, int ld, int lane) {
    const __half* p = base + (size_t)(row + (lane & 7) + ((lane >> 3) & 1) * 8) * ld
                           + col + (lane >> 4) * 8;
    unsigned a = smem_u32(p);
    asm volatile("ldmatrix.sync.aligned.m8n8.x4.shared.b16 {%0,%1,%2,%3},[%4];\n"
                 : "=r"(r[0]), "=r"(r[1]), "=r"(r[2]), "=r"(r[3]) : "r"(a));
}

__device__ __forceinline__ void ldsm_x2(unsigned r[2], const __half* base,
                                        int nrow, int kcol, int ld, int lane) {
    const __half* p = base + (size_t)(nrow + (lane & 7)) * ld
                           + kcol + ((lane >> 3) & 1) * 8;
    unsigned a = smem_u32(p);
    asm volatile("ldmatrix.sync.aligned.m8n8.x2.shared.b16 {%0,%1},[%2];\n"
                 : "=r"(r[0]), "=r"(r[1]) : "r"(a));
}

__device__ __forceinline__ void mma16816(float c[4], const unsigned a[4], const unsigned b[2]) {
    asm volatile("mma.sync.aligned.m16n8k16.row.col.f32.f16.f16.f32 "
                 "{%0,%1,%2,%3},{%4,%5,%6,%7},{%8,%9},{%0,%1,%2,%3};\n"
                 : "+f"(c[0]), "+f"(c[1]), "+f"(c[2]), "+f"(c[3])
                 : "r"(a[0]), "r"(a[1]), "r"(a[2]), "r"(a[3]), "r"(b[0]), "r"(b[1]));
}

// =====================================================================
// Kernel 1: projections.  Y = X @ W^T + b  (2048 x 512 x 512), 3 matrices.
// =====================================================================
__global__ __launch_bounds__(256)
void proj_kernel(const float* __restrict__ Xq, const float* __restrict__ Xk,
                 const float* __restrict__ Xv,
                 const float* __restrict__ Wq, const float* __restrict__ bq,
                 const float* __restrict__ Wk, const float* __restrict__ bk,
                 const float* __restrict__ Wv, const float* __restrict__ bv) {
    const int which = blockIdx.z;
    const float* X = (which == 0) ? Xq : (which == 1) ? Xk : Xv;
    const float* W = (which == 0) ? Wq : (which == 1) ? Wk : Wv;
    const float* bias = (which == 0) ? bq : (which == 1) ? bk : bv;

    __shared__ __half As[128 * 72];
    __shared__ __half Bs[64 * 72];

    const int row0 = blockIdx.x * 128;
    const int j0 = blockIdx.y * 64;
    const int tid = threadIdx.x;
    const int warp = tid >> 5, lane = tid & 31;
    const int wn = warp & 3, wc = warp >> 2;

    float acc[2][4][4] = {};
    float4 ra[8], rb[4];

    #pragma unroll
    for (int it = 0; it < 8; it++) {
        int idx = tid + it * 256;
        int r = idx >> 4, cf = (idx & 15) << 2;
        ra[it] = __ldg(reinterpret_cast<const float4*>(X + (size_t)(row0 + r) * DM + cf));
    }
    #pragma unroll
    for (int it = 0; it < 4; it++) {
        int idx = tid + it * 256;
        int r = idx >> 4, cf = (idx & 15) << 2;
        rb[it] = __ldg(reinterpret_cast<const float4*>(W + (size_t)(j0 + r) * DM + cf));
    }

    for (int kc8 = 0; kc8 < 8; kc8++) {
        #pragma unroll
        for (int it = 0; it < 8; it++) {
            int idx = tid + it * 256;
            int r = idx >> 4, cf = (idx & 15) << 2;
            __half2* dst = reinterpret_cast<__half2*>(&As[r * 72 + cf]);
            dst[0] = __floats2half2_rn(ra[it].x, ra[it].y);
            dst[1] = __floats2half2_rn(ra[it].z, ra[it].w);
        }
        #pragma unroll
        for (int it = 0; it < 4; it++) {
            int idx = tid + it * 256;
            int r = idx >> 4, cf = (idx & 15) << 2;
            __half2* dst = reinterpret_cast<__half2*>(&Bs[r * 72 + cf]);
            dst[0] = __floats2half2_rn(rb[it].x, rb[it].y);
            dst[1] = __floats2half2_rn(rb[it].z, rb[it].w);
        }
        __syncthreads();

        if (kc8 < 7) {
            int kc = (kc8 + 1) * 64;
            #pragma unroll
            for (int it = 0; it < 8; it++) {
                int idx = tid + it * 256;
                int r = idx >> 4, cf = (idx & 15) << 2;
                ra[it] = __ldg(reinterpret_cast<const float4*>(
                    X + (size_t)(row0 + r) * DM + kc + cf));
            }
            #pragma unroll
            for (int it = 0; it < 4; it++) {
                int idx = tid + it * 256;
                int r = idx >> 4, cf = (idx & 15) << 2;
                rb[it] = __ldg(reinterpret_cast<const float4*>(
                    W + (size_t)(j0 + r) * DM + kc + cf));
            }
        }

        #pragma unroll
        for (int kt = 0; kt < 4; kt++) {
            unsigned af[2][4], bf[4][2];
            #pragma unroll
            for (int mt = 0; mt < 2; mt++)
                ldsm_x4(af[mt], As, wn * 32 + mt * 16, kt * 16, 72, lane);
            #pragma unroll
            for (int nt = 0; nt < 4; nt++)
                ldsm_x2(bf[nt], Bs, wc * 32 + nt * 8, kt * 16, 72, lane);
            #pragma unroll
            for (int mt = 0; mt < 2; mt++)
                #pragma unroll
                for (int nt = 0; nt < 4; nt++)
                    mma16816(acc[mt][nt], af[mt], bf[nt]);
        }
        __syncthreads();
    }

    const int h = j0 >> 6;
    #pragma unroll
    for (int mt = 0; mt < 2; mt++) {
        int rg = row0 + wn * 32 + mt * 16 + (lane >> 2);
        #pragma unroll
        for (int nt = 0; nt < 4; nt++) {
            int j = j0 + wc * 32 + nt * 8 + 2 * (lane & 3);
            float b0 = __ldg(bias + j), b1 = __ldg(bias + j + 1);
            #pragma unroll
            for (int hr = 0; hr < 2; hr++) {
                int r = rg + hr * 8;
                int bi = r >> 10, seq = r & 1023;
                float v0 = acc[mt][nt][hr * 2 + 0] + b0;
                float v1 = acc[mt][nt][hr * 2 + 1] + b1;
                int c = j & 63;
                size_t bh = (size_t)(bi * HH + h);
                if (which == 2) {
                    vt_g[(bh * CC + c) * MM + seq]     = __float2half_rn(v0);
                    vt_g[(bh * CC + c + 1) * MM + seq] = __float2half_rn(v1);
                } else {
                    __half* dst = (which == 0) ? qh_g : kh_g;
                    *reinterpret_cast<__half2*>(&dst[(bh * NN + seq) * CC + c]) =
                        __floats2half2_rn(v0, v1);
                }
            }
        }
    }
}

// =====================================================================
// Kernel 2 (FUSED): QK -> Gs f32; pass A sums; pass B: exp+attn write+AV.
//   AV warp layout: warp = (s, k-half, n-group); A-fragment loaded once
//   per kt and reused across the warp's 4 n-tiles (32 cols).
// grid: (64 n-tiles, H, B) = 1024 CTAs, 512 threads, 2 CTAs/SM.
// =====================================================================
#define GS_STRIDE 1032
#define GS_OFF   0
#define KV_OFF   (16 * GS_STRIDE * 4)            // 66048
#define PS_OFF   (KV_OFF + 128 * 72 * 2)         // 84480
#define QS_OFF   (PS_OFF + 4 * 16 * 136 * 2)     // 101888
#define US_OFF   (QS_OFF + 16 * 72 * 2)          // 104192
#define US_STRIDE 1056
#define K2_SMEM  (US_OFF + 4 * US_STRIDE * 2)    // 112640

__global__ __launch_bounds__(512, 2)
void attn_kernel(float* __restrict__ hidden_out, float* __restrict__ attn_out,
                 const float* __restrict__ qsub, const float* __restrict__ ksub) {
    extern __shared__ char smem[];
    float*  Gs = reinterpret_cast<float*>(smem + GS_OFF);   // 16 x 1032 f32
    __half* kv = reinterpret_cast<__half*>(smem + KV_OFF);  // K:128x72 / V:64x136
    __half* Ps = reinterpret_cast<__half*>(smem + PS_OFF);  // [4][16][136] f16
    __half* qs = reinterpret_cast<__half*>(smem + QS_OFF);  // 16 x 72 f16
    __half* us = reinterpret_cast<__half*>(smem + US_OFF);  // ksub fp16 [4][1056]
    float*  red = reinterpret_cast<float*>(smem + KV_OFF);  // reduction (reuses kv)

    const int n0 = blockIdx.x * 16;
    const int h = blockIdx.y, b = blockIdx.z;
    const size_t bh = (size_t)b * HH + h;
    const int tid = threadIdx.x, warp = tid >> 5, lane = tid & 31;

    // prefetch K chunk 0 into regs
    uint4 pk[2];
    #pragma unroll
    for (int it = 0; it < 2; it++) {
        int idx = tid + it * 512;
        int r = idx >> 3, u = idx & 7;
        pk[it] = *reinterpret_cast<const uint4*>(kh_g + (bh * MM + r) * CC + u * 8);
    }
    // stage q tile (16 x 64 f16): 128 uint4
    if (tid < 128) {
        int r = tid >> 3, u = tid & 7;
        *reinterpret_cast<uint4*>(&qs[r * 72 + u * 8]) =
            *reinterpret_cast<const uint4*>(qh_g + (bh * NN + n0 + r) * CC + u * 8);
    }
    // stage ksub fp16: 4 x 1024 floats
    #pragma unroll
    for (int it = 0; it < 2; it++) {
        int idx = tid + it * 512;
        int s = idx >> 8, mf = (idx & 255) << 2;
        float4 d = __ldg(reinterpret_cast<const float4*>(
            ksub + ((size_t)b * SS + s) * MM + mf));
        __half2* dst = reinterpret_cast<__half2*>(&us[s * US_STRIDE + mf]);
        dst[0] = __floats2half2_rn(d.x, d.y);
        dst[1] = __floats2half2_rn(d.z, d.w);
    }
    __syncthreads();

    unsigned afr[4][4];
    #pragma unroll
    for (int kt = 0; kt < 4; kt++)
        ldsm_x4(afr[kt], qs, 0, kt * 16, 72, lane);

    // ---- QK: per 128-m chunk, warp w computes cols w*8..w*8+7 ----
    for (int mc = 0; mc < 8; mc++) {
        if (mc) __syncthreads();
        #pragma unroll
        for (int it = 0; it < 2; it++) {
            int idx = tid + it * 512;
            int r = idx >> 3, u = idx & 7;
            *reinterpret_cast<uint4*>(&kv[r * 72 + u * 8]) = pk[it];
        }
        __syncthreads();
        if (mc < 7) {
            #pragma unroll
            for (int it = 0; it < 2; it++) {
                int idx = tid + it * 512;
                int r = idx >> 3, u = idx & 7;
                pk[it] = *reinterpret_cast<const uint4*>(
                    kh_g + (bh * MM + (mc + 1) * 128 + r) * CC + u * 8);
            }
        }
        float acc[4] = {};
        #pragma unroll
        for (int kt = 0; kt < 4; kt++) {
            unsigned bfr[2];
            ldsm_x2(bfr, kv, warp * 8, kt * 16, 72, lane);
            mma16816(acc, afr[kt], bfr);
        }
        int r = lane >> 2;
        int c0 = mc * 128 + warp * 8 + 2 * (lane & 3);
        Gs[r * GS_STRIDE + c0]           = acc[0];
        Gs[r * GS_STRIDE + c0 + 1]       = acc[1];
        Gs[(r + 8) * GS_STRIDE + c0]     = acc[2];
        Gs[(r + 8) * GS_STRIDE + c0 + 1] = acc[3];
    }
    __syncthreads();

    // prefetch V chunk 0 (overlaps pass A compute)
    uint4 pv[2];
    #pragma unroll
    for (int it = 0; it < 2; it++) {
        int idx = tid + it * 512;
        int r = idx >> 4, u = idx & 15;
        pv[it] = *reinterpret_cast<const uint4*>(vt_g + (bh * CC + r) * MM + u * 8);
    }

    // ---- pass A: row sums (warp w owns row w); ksub from smem fp16 ----
    float cs[4], inv[4];
    #pragma unroll
    for (int s = 0; s < SS; s++)
        cs[s] = SCALE * __ldg(qsub + ((size_t)b * SS + s) * NN + n0 + warp);

    {
        float sum[4] = {0.f, 0.f, 0.f, 0.f};
        #pragma unroll
        for (int j = 0; j < 8; j++) {
            int m = j * 128 + lane * 4;
            float4 g = *reinterpret_cast<const float4*>(&Gs[warp * GS_STRIDE + m]);
            #pragma unroll
            for (int s = 0; s < SS; s++) {
                const __half2* dp = reinterpret_cast<const __half2*>(&us[s * US_STRIDE + m]);
                float2 d01 = __half22float2(dp[0]);
                float2 d23 = __half22float2(dp[1]);
                sum[s] += __expf(cs[s] * d01.x * g.x) + __expf(cs[s] * d01.y * g.y)
                        + __expf(cs[s] * d23.x * g.z) + __expf(cs[s] * d23.y * g.w);
            }
        }
        #pragma unroll
        for (int s = 0; s < SS; s++) {
            #pragma unroll
            for (int o = 16; o; o >>= 1)
                sum[s] += __shfl_xor_sync(0xffffffffu, sum[s], o);
            inv[s] = 1.f / sum[s];
        }
    }

    // ---- pass B: AV warp layout: s_own = warp>>2, kh_ = (warp>>1)&1, ng = warp&1
    float accB[4][4] = {};
    const int s_own = warp >> 2;
    const int kh_ = (warp >> 1) & 1;
    const int ng = warp & 1;

    for (int mc = 0; mc < 8; mc++) {
        if (mc) __syncthreads();   // prev mma reads of kv/Ps done
        #pragma unroll
        for (int it = 0; it < 2; it++) {
            int idx = tid + it * 512;
            int r = idx >> 4, u = idx & 15;
            *reinterpret_cast<uint4*>(&kv[r * 136 + u * 8]) = pv[it];
        }
        {
            int m = mc * 128 + lane * 4;
            float4 g = *reinterpret_cast<const float4*>(&Gs[warp * GS_STRIDE + m]);
            #pragma unroll
            for (int s = 0; s < SS; s++) {
                const __half2* dp = reinterpret_cast<const __half2*>(&us[s * US_STRIDE + m]);
                float2 d01 = __half22float2(dp[0]);
                float2 d23 = __half22float2(dp[1]);
                float4 e;
                e.x = __expf(cs[s] * d01.x * g.x) * inv[s];
                e.y = __expf(cs[s] * d01.y * g.y) * inv[s];
                e.z = __expf(cs[s] * d23.x * g.z) * inv[s];
                e.w = __expf(cs[s] * d23.y * g.w) * inv[s];
                *reinterpret_cast<float4*>(
                    attn_out + ((bh * SS + s) * NN + n0 + warp) * (size_t)MM + m) = e;
                __half2* pd = reinterpret_cast<__half2*>(&Ps[(s * 16 + warp) * 136 + lane * 4]);
                pd[0] = __floats2half2_rn(e.x, e.y);
                pd[1] = __floats2half2_rn(e.z, e.w);
            }
        }
        __syncthreads();
        if (mc < 7) {
            #pragma unroll
            for (int it = 0; it < 2; it++) {
                int idx = tid + it * 512;
                int r = idx >> 4, u = idx & 15;
                pv[it] = *reinterpret_cast<const uint4*>(
                    vt_g + (bh * CC + r) * MM + (mc + 1) * 128 + u * 8);
            }
        }
        // AV mma: A-frag loaded once per kt, reused across 4 n-tiles
        #pragma unroll
        for (int kt = 0; kt < 4; kt++) {
            int kk = kh_ * 4 + kt;
            unsigned af[4];
            ldsm_x4(af, Ps + s_own * 16 * 136, 0, kk * 16, 136, lane);
            #pragma unroll
            for (int nt = 0; nt < 4; nt++) {
                unsigned bf[2];
                ldsm_x2(bf, kv, ng * 32 + nt * 8, kk * 16, 136, lane);
                mma16816(accB[nt], af, bf);
            }
        }
    }
    __syncthreads();

    // 2-way k-split reduction + hidden write
    if (kh_ == 1) {
        #pragma unroll
        for (int nt = 0; nt < 4; nt++)
            *reinterpret_cast<float4*>(
                &red[(((s_own * 2 + ng) * 4 + nt) * 32 + lane) * 4]) =
                make_float4(accB[nt][0], accB[nt][1], accB[nt][2], accB[nt][3]);
    }
    __syncthreads();
    if (kh_ == 0) {
        #pragma unroll
        for (int nt = 0; nt < 4; nt++) {
            float4 p = *reinterpret_cast<const float4*>(
                &red[(((s_own * 2 + ng) * 4 + nt) * 32 + lane) * 4]);
            float v0 = accB[nt][0] + p.x, v1 = accB[nt][1] + p.y;
            float v2 = accB[nt][2] + p.z, v3 = accB[nt][3] + p.w;
            int r0 = lane >> 2;
            int c = ng * 32 + nt * 8 + 2 * (lane & 3);
            size_t base = ((size_t)(b * SS + s_own) * NN + n0) * DM + h * 64 + c;
            *reinterpret_cast<float2*>(&hidden_out[base + (size_t)r0 * DM]) =
                make_float2(v0, v1);
            *reinterpret_cast<float2*>(&hidden_out[base + (size_t)(r0 + 8) * DM]) =
                make_float2(v2, v3);
        }
    }
}

// =====================================================================
extern "C" void kernel_launch(void* const* d_in, const int* in_sizes, int n_in,
                              void* d_out, int out_size) {
    (void)in_sizes; (void)n_in; (void)out_size;
    const float* Xq   = (const float*)d_in[0];
    const float* Xk   = (const float*)d_in[1];
    const float* Xv   = (const float*)d_in[2];
    const float* qsub = (const float*)d_in[3];
    const float* ksub = (const float*)d_in[4];
    const float* Wq   = (const float*)d_in[5];
    const float* bq   = (const float*)d_in[6];
    const float* Wk   = (const float*)d_in[7];
    const float* bk   = (const float*)d_in[8];
    const float* Wv   = (const float*)d_in[9];
    const float* bv   = (const float*)d_in[10];

    float* out = (float*)d_out;
    float* attn_out = out + (size_t)BB * SS * NN * DM;  // hidden first, attn second

    cudaFuncSetAttribute(attn_kernel, cudaFuncAttributeMaxDynamicSharedMemorySize, K2_SMEM);

    proj_kernel<<<dim3(16, 8, 3), 256>>>(Xq, Xk, Xv, Wq, bq, Wk, bk, Wv, bv);
    attn_kernel<<<dim3(64, 8, 2), 512, K2_SMEM>>>(out, attn_out, qsub, ksub);
}

// round 7
// speedup vs baseline: 1.8626x; 1.0367x over previous
#include <cuda_runtime.h>
#include <cuda_fp16.h>

// Problem constants
#define BB 2
#define HH 8
#define NN 1024
#define MM 1024
#define SS 4
#define CC 64
#define DM 512
#define SCALE 0.125f   // 1/sqrt(64)

// fp16 scratch (device globals: allocation-free)
__device__ __half qh_g[(size_t)BB*HH*NN*CC];   // [bh][n][c]
__device__ __half kh_g[(size_t)BB*HH*MM*CC];   // [bh][m][c]
__device__ __half vt_g[(size_t)BB*HH*CC*MM];   // [bh][c][m]  (transposed V)

// ---------------------------------------------------------------- mma helpers
__device__ __forceinline__ unsigned smem_u32(const void* p) {
    return (unsigned)__cvta_generic_to_shared(p);
}

__device__ __forceinline__ void ldsm_x4(unsigned r[4], const __half* base,
                                        int row, int col, int ld, int lane) {
    const __half* p = base + (size_t)(row + (lane & 7) + ((lane >> 3) & 1) * 8) * ld
                           + col + (lane >> 4) * 8;
    unsigned a = smem_u32(p);
    asm volatile("ldmatrix.sync.aligned.m8n8.x4.shared.b16 {%0,%1,%2,%3},[%4];\n"
                 : "=r"(r[0]), "=r"(r[1]), "=r"(r[2]), "=r"(r[3]) : "r"(a));
}

// B-frag pair over two n-tiles (nrow, nrow+8), same kcol: r[0..1]=tile0, r[2..3]=tile1
__device__ __forceinline__ void ldsm_b_x4n(unsigned r[4], const __half* base,
                                           int nrow, int kcol, int ld, int lane) {
    const __half* p = base + (size_t)(nrow + (lane & 7) + ((lane >> 4) & 1) * 8) * ld
                           + kcol + ((lane >> 3) & 1) * 8;
    unsigned a = smem_u32(p);
    asm volatile("ldmatrix.sync.aligned.m8n8.x4.shared.b16 {%0,%1,%2,%3},[%4];\n"
                 : "=r"(r[0]), "=r"(r[1]), "=r"(r[2]), "=r"(r[3]) : "r"(a));
}

// B-frag pair over two k-tiles (kcol, kcol+16), same nrow: r[0..1]=kt, r[2..3]=kt+1
__device__ __forceinline__ void ldsm_b_x4k(unsigned r[4], const __half* base,
                                           int nrow, int kcol, int ld, int lane) {
    const __half* p = base + (size_t)(nrow + (lane & 7)) * ld
                           + kcol + ((lane >> 3) & 1) * 8 + ((lane >> 4) & 1) * 16;
    unsigned a = smem_u32(p);
    asm volatile("ldmatrix.sync.aligned.m8n8.x4.shared.b16 {%0,%1,%2,%3},[%4];\n"
                 : "=r"(r[0]), "=r"(r[1]), "=r"(r[2]), "=r"(r[3]) : "r"(a));
}

__device__ __forceinline__ void mma16816(float c[4], const unsigned a[4], const unsigned b[2]) {
    asm volatile("mma.sync.aligned.m16n8k16.row.col.f32.f16.f16.f32 "
                 "{%0,%1,%2,%3},{%4,%5,%6,%7},{%8,%9},{%0,%1,%2,%3};\n"
                 : "+f"(c[0]), "+f"(c[1]), "+f"(c[2]), "+f"(c[3])
                 : "r"(a[0]), "r"(a[1]), "r"(a[2]), "r"(a[3]), "r"(b[0]), "r"(b[1]));
}

// =====================================================================
// Kernel 1: projections, 64x64 tiles.  grid (32, 8, 3), 256 threads.
// =====================================================================
__global__ __launch_bounds__(256)
void proj_kernel(const float* __restrict__ Xq, const float* __restrict__ Xk,
                 const float* __restrict__ Xv,
                 const float* __restrict__ Wq, const float* __restrict__ bq,
                 const float* __restrict__ Wk, const float* __restrict__ bk,
                 const float* __restrict__ Wv, const float* __restrict__ bv) {
    const int which = blockIdx.z;
    const float* X = (which == 0) ? Xq : (which == 1) ? Xk : Xv;
    const float* W = (which == 0) ? Wq : (which == 1) ? Wk : Wv;
    const float* bias = (which == 0) ? bq : (which == 1) ? bk : bv;

    __shared__ __half As[64 * 72];
    __shared__ __half Bs[64 * 72];

    const int row0 = blockIdx.x * 64;
    const int j0 = blockIdx.y * 64;           // head = blockIdx.y
    const int tid = threadIdx.x;
    const int warp = tid >> 5, lane = tid & 31;
    const int wn = warp & 1, wc = warp >> 1;  // 2x4 warps, 32x16 warp tiles

    float acc[2][2][4] = {};
    float4 ra[4], rb[4];

    #pragma unroll
    for (int it = 0; it < 4; it++) {
        int idx = tid + it * 256;
        int r = idx >> 4, cf = (idx & 15) << 2;
        ra[it] = __ldg(reinterpret_cast<const float4*>(X + (size_t)(row0 + r) * DM + cf));
        rb[it] = __ldg(reinterpret_cast<const float4*>(W + (size_t)(j0 + r) * DM + cf));
    }

    for (int kc8 = 0; kc8 < 8; kc8++) {
        if (kc8) __syncthreads();
        #pragma unroll
        for (int it = 0; it < 4; it++) {
            int idx = tid + it * 256;
            int r = idx >> 4, cf = (idx & 15) << 2;
            __half2* da = reinterpret_cast<__half2*>(&As[r * 72 + cf]);
            da[0] = __floats2half2_rn(ra[it].x, ra[it].y);
            da[1] = __floats2half2_rn(ra[it].z, ra[it].w);
            __half2* db = reinterpret_cast<__half2*>(&Bs[r * 72 + cf]);
            db[0] = __floats2half2_rn(rb[it].x, rb[it].y);
            db[1] = __floats2half2_rn(rb[it].z, rb[it].w);
        }
        __syncthreads();

        if (kc8 < 7) {
            int kc = (kc8 + 1) * 64;
            #pragma unroll
            for (int it = 0; it < 4; it++) {
                int idx = tid + it * 256;
                int r = idx >> 4, cf = (idx & 15) << 2;
                ra[it] = __ldg(reinterpret_cast<const float4*>(
                    X + (size_t)(row0 + r) * DM + kc + cf));
                rb[it] = __ldg(reinterpret_cast<const float4*>(
                    W + (size_t)(j0 + r) * DM + kc + cf));
            }
        }

        #pragma unroll
        for (int kt = 0; kt < 4; kt++) {
            unsigned af[2][4], bf[4];
            #pragma unroll
            for (int mt = 0; mt < 2; mt++)
                ldsm_x4(af[mt], As, wn * 32 + mt * 16, kt * 16, 72, lane);
            ldsm_b_x4n(bf, Bs, wc * 16, kt * 16, 72, lane);
            #pragma unroll
            for (int mt = 0; mt < 2; mt++) {
                mma16816(acc[mt][0], af[mt], bf);
                mma16816(acc[mt][1], af[mt], bf + 2);
            }
        }
    }

    const int h = blockIdx.y;
    #pragma unroll
    for (int mt = 0; mt < 2; mt++) {
        int rg = row0 + wn * 32 + mt * 16 + (lane >> 2);
        #pragma unroll
        for (int nt = 0; nt < 2; nt++) {
            int j = j0 + wc * 16 + nt * 8 + 2 * (lane & 3);
            float b0 = __ldg(bias + j), b1 = __ldg(bias + j + 1);
            #pragma unroll
            for (int hr = 0; hr < 2; hr++) {
                int r = rg + hr * 8;
                int bi = r >> 10, seq = r & 1023;
                float v0 = acc[mt][nt][hr * 2 + 0] + b0;
                float v1 = acc[mt][nt][hr * 2 + 1] + b1;
                int c = j & 63;
                size_t bh = (size_t)(bi * HH + h);
                if (which == 2) {
                    vt_g[(bh * CC + c) * MM + seq]     = __float2half_rn(v0);
                    vt_g[(bh * CC + c + 1) * MM + seq] = __float2half_rn(v1);
                } else {
                    __half* dst = (which == 0) ? qh_g : kh_g;
                    *reinterpret_cast<__half2*>(&dst[(bh * NN + seq) * CC + c]) =
                        __floats2half2_rn(v0, v1);
                }
            }
        }
    }
}

// =====================================================================
// Kernel 2 (FUSED): fp16 Gs; double-buffered K (QK) and V+Ps (pass B);
// one sync per chunk.  grid (64, 8, 2) = 1024 CTAs, 512 thr, 2 CTAs/SM.
// =====================================================================
#define GS_STRIDE 1032
#define GS_OFF   0                               // 16 x 1032 f16 = 33024
#define KV_OFF   33024                           // 2 x 18432 (K 128x72 / V 64x136)
#define PS_OFF   69888                           // 2 x 17408 ([4][16][136] f16)
#define US_OFF   104704                          // 4 x 1056 f16 = 8448
#define US_STRIDE 1056
#define K2_SMEM  113152

__global__ __launch_bounds__(512, 2)
void attn_kernel(float* __restrict__ hidden_out, float* __restrict__ attn_out,
                 const float* __restrict__ qsub, const float* __restrict__ ksub) {
    extern __shared__ char smem[];
    __half* Gs = reinterpret_cast<__half*>(smem + GS_OFF);
    __half* qs = reinterpret_cast<__half*>(smem + PS_OFF);   // overlay (pre-pass-B)
    __half* us = reinterpret_cast<__half*>(smem + US_OFF);
    float*  red = reinterpret_cast<float*>(smem + KV_OFF);   // final reduction (buf0)

    const int n0 = blockIdx.x * 16;
    const int h = blockIdx.y, b = blockIdx.z;
    const size_t bh = (size_t)b * HH + h;
    const int tid = threadIdx.x, warp = tid >> 5, lane = tid & 31;

    // prefetch K chunk 0
    uint4 pk[2];
    #pragma unroll
    for (int it = 0; it < 2; it++) {
        int idx = tid + it * 512;
        int r = idx >> 3, u = idx & 7;
        pk[it] = *reinterpret_cast<const uint4*>(kh_g + (bh * MM + r) * CC + u * 8);
    }
    // stage q tile (16 x 64 f16)
    if (tid < 128) {
        int r = tid >> 3, u = tid & 7;
        *reinterpret_cast<uint4*>(&qs[r * 72 + u * 8]) =
            *reinterpret_cast<const uint4*>(qh_g + (bh * NN + n0 + r) * CC + u * 8);
    }
    // stage ksub fp16
    #pragma unroll
    for (int it = 0; it < 2; it++) {
        int idx = tid + it * 512;
        int s = idx >> 8, mf = (idx & 255) << 2;
        float4 d = __ldg(reinterpret_cast<const float4*>(
            ksub + ((size_t)b * SS + s) * MM + mf));
        __half2* dst = reinterpret_cast<__half2*>(&us[s * US_STRIDE + mf]);
        dst[0] = __floats2half2_rn(d.x, d.y);
        dst[1] = __floats2half2_rn(d.z, d.w);
    }
    __syncthreads();

    unsigned afr[4][4];
    #pragma unroll
    for (int kt = 0; kt < 4; kt++)
        ldsm_x4(afr[kt], qs, 0, kt * 16, 72, lane);

    // ---- QK: 8 chunks of 128 m, double-buffered K, one sync/chunk ----
    for (int mc = 0; mc < 8; mc++) {
        __half* kb = reinterpret_cast<__half*>(smem + KV_OFF + (mc & 1) * 18432);
        #pragma unroll
        for (int it = 0; it < 2; it++) {
            int idx = tid + it * 512;
            int r = idx >> 3, u = idx & 7;
            *reinterpret_cast<uint4*>(&kb[r * 72 + u * 8]) = pk[it];
        }
        if (mc < 7) {
            #pragma unroll
            for (int it = 0; it < 2; it++) {
                int idx = tid + it * 512;
                int r = idx >> 3, u = idx & 7;
                pk[it] = *reinterpret_cast<const uint4*>(
                    kh_g + (bh * MM + (mc + 1) * 128 + r) * CC + u * 8);
            }
        }
        __syncthreads();
        float acc[4] = {};
        #pragma unroll
        for (int kp = 0; kp < 2; kp++) {
            unsigned bfr[4];
            ldsm_b_x4k(bfr, kb, warp * 8, kp * 32, 72, lane);
            mma16816(acc, afr[kp * 2 + 0], bfr);
            mma16816(acc, afr[kp * 2 + 1], bfr + 2);
        }
        int r = lane >> 2;
        int c0 = mc * 128 + warp * 8 + 2 * (lane & 3);
        *reinterpret_cast<__half2*>(&Gs[r * GS_STRIDE + c0]) =
            __floats2half2_rn(acc[0], acc[1]);
        *reinterpret_cast<__half2*>(&Gs[(r + 8) * GS_STRIDE + c0]) =
            __floats2half2_rn(acc[2], acc[3]);
    }
    __syncthreads();

    // prefetch V chunk 0
    uint4 pv[2];
    #pragma unroll
    for (int it = 0; it < 2; it++) {
        int idx = tid + it * 512;
        int r = idx >> 4, u = idx & 15;
        pv[it] = *reinterpret_cast<const uint4*>(vt_g + (bh * CC + r) * MM + u * 8);
    }

    // ---- pass A: row sums (warp w owns row w) ----
    float cs[4], inv[4];
    #pragma unroll
    for (int s = 0; s < SS; s++)
        cs[s] = SCALE * __ldg(qsub + ((size_t)b * SS + s) * NN + n0 + warp);
    {
        float sum[4] = {0.f, 0.f, 0.f, 0.f};
        #pragma unroll
        for (int j = 0; j < 8; j++) {
            int m = j * 128 + lane * 4;
            uint2 gu = *reinterpret_cast<const uint2*>(&Gs[warp * GS_STRIDE + m]);
            float2 g01 = __half22float2(*reinterpret_cast<__half2*>(&gu.x));
            float2 g23 = __half22float2(*reinterpret_cast<__half2*>(&gu.y));
            #pragma unroll
            for (int s = 0; s < SS; s++) {
                uint2 du = *reinterpret_cast<const uint2*>(&us[s * US_STRIDE + m]);
                float2 d01 = __half22float2(*reinterpret_cast<__half2*>(&du.x));
                float2 d23 = __half22float2(*reinterpret_cast<__half2*>(&du.y));
                sum[s] += __expf(cs[s] * d01.x * g01.x) + __expf(cs[s] * d01.y * g01.y)
                        + __expf(cs[s] * d23.x * g23.x) + __expf(cs[s] * d23.y * g23.y);
            }
        }
        #pragma unroll
        for (int s = 0; s < SS; s++) {
            #pragma unroll
            for (int o = 16; o; o >>= 1)
                sum[s] += __shfl_xor_sync(0xffffffffu, sum[s], o);
            inv[s] = 1.f / sum[s];
        }
    }

    // ---- pass B: double-buffered V + Ps, one sync/chunk ----
    float accB[4][4] = {};
    const int s_own = warp >> 2;
    const int kh_ = (warp >> 1) & 1;
    const int ng = warp & 1;

    for (int mc = 0; mc < 8; mc++) {
        __half* vb = reinterpret_cast<__half*>(smem + KV_OFF + (mc & 1) * 18432);
        __half* pb = reinterpret_cast<__half*>(smem + PS_OFF + (mc & 1) * 17408);
        #pragma unroll
        for (int it = 0; it < 2; it++) {
            int idx = tid + it * 512;
            int r = idx >> 4, u = idx & 15;
            *reinterpret_cast<uint4*>(&vb[r * 136 + u * 8]) = pv[it];
        }
        {
            int m = mc * 128 + lane * 4;
            uint2 gu = *reinterpret_cast<const uint2*>(&Gs[warp * GS_STRIDE + m]);
            float2 g01 = __half22float2(*reinterpret_cast<__half2*>(&gu.x));
            float2 g23 = __half22float2(*reinterpret_cast<__half2*>(&gu.y));
            #pragma unroll
            for (int s = 0; s < SS; s++) {
                uint2 du = *reinterpret_cast<const uint2*>(&us[s * US_STRIDE + m]);
                float2 d01 = __half22float2(*reinterpret_cast<__half2*>(&du.x));
                float2 d23 = __half22float2(*reinterpret_cast<__half2*>(&du.y));
                float4 e;
                e.x = __expf(cs[s] * d01.x * g01.x) * inv[s];
                e.y = __expf(cs[s] * d01.y * g01.y) * inv[s];
                e.z = __expf(cs[s] * d23.x * g23.x) * inv[s];
                e.w = __expf(cs[s] * d23.y * g23.y) * inv[s];
                __stcs(reinterpret_cast<float4*>(
                    attn_out + ((bh * SS + s) * NN + n0 + warp) * (size_t)MM + m), e);
                __half2* pd = reinterpret_cast<__half2*>(&pb[(s * 16 + warp) * 136 + lane * 4]);
                pd[0] = __floats2half2_rn(e.x, e.y);
                pd[1] = __floats2half2_rn(e.z, e.w);
            }
        }
        if (mc < 7) {
            #pragma unroll
            for (int it = 0; it < 2; it++) {
                int idx = tid + it * 512;
                int r = idx >> 4, u = idx & 15;
                pv[it] = *reinterpret_cast<const uint4*>(
                    vt_g + (bh * CC + r) * MM + (mc + 1) * 128 + u * 8);
            }
        }
        __syncthreads();
        #pragma unroll
        for (int kt = 0; kt < 4; kt++) {
            int kk = kh_ * 4 + kt;
            unsigned af[4];
            ldsm_x4(af, pb + s_own * 16 * 136, 0, kk * 16, 136, lane);
            unsigned bf0[4], bf1[4];
            ldsm_b_x4n(bf0, vb, ng * 32, kk * 16, 136, lane);
            ldsm_b_x4n(bf1, vb, ng * 32 + 16, kk * 16, 136, lane);
            mma16816(accB[0], af, bf0);
            mma16816(accB[1], af, bf0 + 2);
            mma16816(accB[2], af, bf1);
            mma16816(accB[3], af, bf1 + 2);
        }
    }
    __syncthreads();

    // 2-way k-split reduction + hidden write (red overlays buf0)
    if (kh_ == 1) {
        #pragma unroll
        for (int nt = 0; nt < 4; nt++)
            *reinterpret_cast<float4*>(
                &red[(((s_own * 2 + ng) * 4 + nt) * 32 + lane) * 4]) =
                make_float4(accB[nt][0], accB[nt][1], accB[nt][2], accB[nt][3]);
    }
    __syncthreads();
    if (kh_ == 0) {
        #pragma unroll
        for (int nt = 0; nt < 4; nt++) {
            float4 p = *reinterpret_cast<const float4*>(
                &red[(((s_own * 2 + ng) * 4 + nt) * 32 + lane) * 4]);
            float v0 = accB[nt][0] + p.x, v1 = accB[nt][1] + p.y;
            float v2 = accB[nt][2] + p.z, v3 = accB[nt][3] + p.w;
            int r0 = lane >> 2;
            int c = ng * 32 + nt * 8 + 2 * (lane & 3);
            size_t base = ((size_t)(b * SS + s_own) * NN + n0) * DM + h * 64 + c;
            *reinterpret_cast<float2*>(&hidden_out[base + (size_t)r0 * DM]) =
                make_float2(v0, v1);
            *reinterpret_cast<float2*>(&hidden_out[base + (size_t)(r0 + 8) * DM]) =
                make_float2(v2, v3);
        }
    }
}

// =====================================================================
extern "C" void kernel_launch(void* const* d_in, const int* in_sizes, int n_in,
                              void* d_out, int out_size) {
    (void)in_sizes; (void)n_in; (void)out_size;
    const float* Xq   = (const float*)d_in[0];
    const float* Xk   = (const float*)d_in[1];
    const float* Xv   = (const float*)d_in[2];
    const float* qsub = (const float*)d_in[3];
    const float* ksub = (const float*)d_in[4];
    const float* Wq   = (const float*)d_in[5];
    const float* bq   = (const float*)d_in[6];
    const float* Wk   = (const float*)d_in[7];
    const float* bk   = (const float*)d_in[8];
    const float* Wv   = (const float*)d_in[9];
    const float* bv   = (const float*)d_in[10];

    float* out = (float*)d_out;
    float* attn_out = out + (size_t)BB * SS * NN * DM;  // hidden first, attn second

    cudaFuncSetAttribute(attn_kernel, cudaFuncAttributeMaxDynamicSharedMemorySize, K2_SMEM);

    proj_kernel<<<dim3(32, 8, 3), 256>>>(Xq, Xk, Xv, Wq, bq, Wk, bk, Wv, bv);
    attn_kernel<<<dim3(64, 8, 2), 512, K2_SMEM>>>(out, attn_out, qsub, ksub);
}